// round 2
// baseline (speedup 1.0000x reference)
#include <cuda_runtime.h>
#include <math.h>

// Problem constants
#define Bb 4
#define Ss 8192
#define Ff 512
#define Nn 64
#define Hh 2048
#define BSr (Bb*Ss)            // 32768 rows

// ---------------- scratch (device globals; no allocations allowed) ----------
__device__ float d_h[BSr*Ff];          // 64MB: h (LN1 out), reused as h2
__device__ float d_x1[BSr*Ff];         // 64MB: first residual result
__device__ float d_g[BSr*Hh];          // 256MB: MLP hidden; first 64MB also used as y-scratch
__device__ float d_buT[256*BSr];       // 32MB: Bu (transposed), scanned in place -> xs
__device__ float d_mods[Bb*6*Ff];      // adaLN modulation
__device__ float d_wbu[256*Ff];        // B_bar combined weight  [ch][f]
__device__ float d_wout[256*Ff];       // C^T @ proj_w combined  [ch][f']
__device__ float d_wd[Ff*Ff];          // diag(D) @ proj_w combined
__device__ float2 d_abar[128];         // per complex channel (0..63 fwd, 64..127 bwd)

// ---------------- prep kernels ----------------------------------------------

// mods = silu(cond) @ ada_w + ada_b     grid(12,4) x 256
__global__ void prep_mods_k(const float* __restrict__ cond,
                            const float* __restrict__ ada_w,
                            const float* __restrict__ ada_b) {
    __shared__ float sc[Ff];
    int b = blockIdx.y;
    for (int i = threadIdx.x; i < Ff; i += 256) {
        float v = cond[b*Ff + i];
        sc[i] = v / (1.0f + expf(-v));
    }
    __syncthreads();
    int j = blockIdx.x * 256 + threadIdx.x;     // 0..3071
    float acc = ada_b[j];
    #pragma unroll 8
    for (int f = 0; f < Ff; f++) acc += sc[f] * ada_w[f*(6*Ff) + j];
    d_mods[b*(6*Ff) + j] = acc;
}

// per-direction SSM discretization -> a_bar, B_bar weight.  grid(128) x 512
__global__ void prep_ssm_k(const float* __restrict__ fla, const float* __restrict__ fai,
                           const float* __restrict__ fbr, const float* __restrict__ fbi,
                           const float* __restrict__ fld,
                           const float* __restrict__ bla, const float* __restrict__ bai,
                           const float* __restrict__ bbr, const float* __restrict__ bbi,
                           const float* __restrict__ bld) {
    int n   = blockIdx.x & 63;
    int dir = blockIdx.x >> 6;
    const float* logAre = dir ? bla : fla;
    const float* Aim    = dir ? bai : fai;
    const float* Bre    = dir ? bbr : fbr;
    const float* Bim    = dir ? bbi : fbi;
    const float* logdt  = dir ? bld : fld;

    float dt   = expf(logdt[n]);
    float Are  = -expf(logAre[n]);
    float Aimv = Aim[n];
    float er   = expf(Are * dt);
    float abr  = er * cosf(Aimv * dt);
    float abi  = er * sinf(Aimv * dt);
    // coef = (a_bar - 1) / (A + 1e-8)
    float dre = Are + 1e-8f, dim = Aimv;
    float den = dre*dre + dim*dim;
    float nre = abr - 1.0f, nim = abi;
    float cre = (nre*dre + nim*dim) / den;
    float cim = (nim*dre - nre*dim) / den;

    if (threadIdx.x == 0) d_abar[dir*64 + n] = make_float2(abr, abi);

    int f = threadIdx.x;                               // 512 threads
    float br = Bre[n*Ff + f], bi = Bim[n*Ff + f];
    d_wbu[(dir*128 + n     )*Ff + f] = cre*br - cim*bi;   // Re(B_bar)
    d_wbu[(dir*128 + 64 + n)*Ff + f] = cre*bi + cim*br;   // Im(B_bar)
}

// W_out[ch][f'] = (+/-) sum_f C[f][n] * proj_w[poff+f][f']   grid(256) x 512
__global__ void prep_wout_k(const float* __restrict__ fcr, const float* __restrict__ fci,
                            const float* __restrict__ bcr, const float* __restrict__ bci,
                            const float* __restrict__ proj_w) {
    int ch  = blockIdx.x;
    int blk = ch >> 6, n = ch & 63;
    const float* C = (blk == 0) ? fcr : (blk == 1) ? fci : (blk == 2) ? bcr : bci;
    float sign = (blk == 1 || blk == 3) ? -1.0f : 1.0f;
    int poff = (blk >= 2) ? Ff : 0;

    __shared__ float sC[Ff];
    for (int i = threadIdx.x; i < Ff; i += 512) sC[i] = C[i*Nn + n];
    __syncthreads();
    int fp = threadIdx.x;
    float acc = 0.0f;
    #pragma unroll 8
    for (int f = 0; f < Ff; f++) acc += sC[f] * proj_w[(poff + f)*Ff + fp];
    d_wout[ch*Ff + fp] = sign * acc;
}

// W_D = diag(D_fwd)@P[0:F] + diag(D_bwd)@P[F:2F]   grid(1024) x 256
__global__ void prep_wd_k(const float* __restrict__ Df, const float* __restrict__ Db,
                          const float* __restrict__ proj_w) {
    int idx = blockIdx.x * 256 + threadIdx.x;   // 0..262143
    int f = idx >> 9;
    d_wd[idx] = Df[f]*proj_w[idx] + Db[f]*proj_w[idx + Ff*Ff];
}

// ---------------- LN + adaLN modulation -------------------------------------
// out = LN(in)*(1+sc)+sh ; moff selects {sh1,sc1} or {sh2,sc2}. grid(32768) x 128
__global__ void ln_mod_k(const float* __restrict__ in, float* __restrict__ out, int moff) {
    int row = blockIdx.x;
    int bb  = row >> 13;
    int tid = threadIdx.x;
    float4 v = ((const float4*)(in + (size_t)row*Ff))[tid];
    float s  = v.x+v.y+v.z+v.w;
    float sq = v.x*v.x + v.y*v.y + v.z*v.z + v.w*v.w;
    #pragma unroll
    for (int o = 16; o > 0; o >>= 1) {
        s  += __shfl_down_sync(0xffffffffu, s,  o);
        sq += __shfl_down_sync(0xffffffffu, sq, o);
    }
    __shared__ float ss[4], ssq[4];
    int w = tid >> 5, l = tid & 31;
    if (l == 0) { ss[w] = s; ssq[w] = sq; }
    __syncthreads();
    if (tid == 0) { ss[0]  = ss[0]+ss[1]+ss[2]+ss[3];
                    ssq[0] = ssq[0]+ssq[1]+ssq[2]+ssq[3]; }
    __syncthreads();
    float mu  = ss[0]  * (1.0f/512.0f);
    float var = ssq[0] * (1.0f/512.0f) - mu*mu;
    float rstd = rsqrtf(var + 1e-5f);
    const float* md = d_mods + bb*(6*Ff) + moff;
    int f = tid*4;
    float4 o4;
    o4.x = (v.x-mu)*rstd*(1.0f+md[Ff+f+0]) + md[f+0];
    o4.y = (v.y-mu)*rstd*(1.0f+md[Ff+f+1]) + md[f+1];
    o4.z = (v.z-mu)*rstd*(1.0f+md[Ff+f+2]) + md[f+2];
    o4.w = (v.w-mu)*rstd*(1.0f+md[Ff+f+3]) + md[f+3];
    ((float4*)(out + (size_t)row*Ff))[tid] = o4;
}

// ---------------- generic tiled fp32 GEMM ------------------------------------
// C[M,N] = A @ B   (TA: 0 = A[m][k] lda=K ; 1 = A stored as AT[k][m], lda = m-stride)
//                  (TB: 0 = B[k][n] ldb=N ; 1 = B stored as BT[n][k], ldb = k-count)
#define BM 128
#define BN 128
#define BK 16

template<int TA, int TB, int EPI>
__global__ __launch_bounds__(256, 2) void gemm_k(
    const float* __restrict__ A, const float* __restrict__ Bm, float* __restrict__ C,
    int M, int N, int K, int lda, int ldb, int ldc,
    const float* __restrict__ aux1, const float* __restrict__ aux2,
    const float* __restrict__ aux3) {
    __shared__ float As[BK][BM + 4];
    __shared__ float Bs[BK][BN + 4];
    int tid = threadIdx.x;
    int tx = tid & 15, ty = tid >> 4;
    int m0 = blockIdx.y * BM, n0 = blockIdx.x * BN;
    float acc[8][8] = {};

    for (int k0 = 0; k0 < K; k0 += BK) {
        // --- load A tile ---
        if (TA == 0) {
            #pragma unroll
            for (int i = 0; i < 2; i++) {
                int idx4 = tid*2 + i;
                int m = idx4 >> 2, kq = idx4 & 3;
                float4 v = *(const float4*)(A + (size_t)(m0+m)*lda + k0 + kq*4);
                As[kq*4+0][m] = v.x; As[kq*4+1][m] = v.y;
                As[kq*4+2][m] = v.z; As[kq*4+3][m] = v.w;
            }
        } else {
            #pragma unroll
            for (int i = 0; i < 2; i++) {
                int idx4 = tid*2 + i;
                int k = idx4 >> 5, mq = idx4 & 31;
                float4 v = *(const float4*)(A + (size_t)(k0+k)*lda + m0 + mq*4);
                *(float4*)&As[k][mq*4] = v;
            }
        }
        // --- load B tile ---
        if (TB == 0) {
            #pragma unroll
            for (int i = 0; i < 2; i++) {
                int idx4 = tid*2 + i;
                int k = idx4 >> 5, nq = idx4 & 31;
                float4 v = *(const float4*)(Bm + (size_t)(k0+k)*ldb + n0 + nq*4);
                *(float4*)&Bs[k][nq*4] = v;
            }
        } else {
            #pragma unroll
            for (int i = 0; i < 2; i++) {
                int idx4 = tid*2 + i;
                int n = idx4 >> 2, kq = idx4 & 3;
                float4 v = *(const float4*)(Bm + (size_t)(n0+n)*ldb + k0 + kq*4);
                Bs[kq*4+0][n] = v.x; Bs[kq*4+1][n] = v.y;
                Bs[kq*4+2][n] = v.z; Bs[kq*4+3][n] = v.w;
            }
        }
        __syncthreads();
        #pragma unroll
        for (int k = 0; k < BK; k++) {
            float a[8], b[8];
            #pragma unroll
            for (int i = 0; i < 8; i++) a[i] = As[k][ty*8 + i];
            #pragma unroll
            for (int j = 0; j < 8; j++) b[j] = Bs[k][tx*8 + j];
            #pragma unroll
            for (int i = 0; i < 8; i++)
                #pragma unroll
                for (int j = 0; j < 8; j++)
                    acc[i][j] = fmaf(a[i], b[j], acc[i][j]);
        }
        __syncthreads();
    }

    // --- epilogue ---
    #pragma unroll
    for (int i = 0; i < 8; i++) {
        int m = m0 + ty*8 + i;
        #pragma unroll
        for (int j = 0; j < 8; j++) {
            int n = n0 + tx*8 + j;
            float v = acc[i][j];
            size_t off = (size_t)m * ldc + n;
            if (EPI == 0) {
                C[off] = v;
            } else if (EPI == 1) {        // x1 = x + g1*(xs_part + h_part + proj_b)
                int bb = m >> 13;
                float y = v + aux1[(size_t)m*Ff + n] + aux2[n];
                float g1 = d_mods[bb*(6*Ff) + 2*Ff + n];
                C[off] = aux3[(size_t)m*Ff + n] + g1 * y;
            } else if (EPI == 2) {        // gelu(tanh approx)(v + b1)
                float x = v + aux1[n];
                float t = tanhf(0.7978845608028654f * (x + 0.044715f * x*x*x));
                C[off] = 0.5f * x * (1.0f + t);
            } else {                      // out = x1 + g2*(v + b2)
                int bb = m >> 13;
                float g2 = d_mods[bb*(6*Ff) + 5*Ff + n];
                C[off] = aux1[off] + g2 * (v + aux2[n]);
            }
        }
    }
}

// ---------------- chunked complex scan (constant multiplier) -----------------
// grid(512) = b*128 + c ; 256 threads, 32 elems/thread, in place on d_buT.
__global__ __launch_bounds__(256) void scan_k(float* __restrict__ buT) {
    int c = blockIdx.x & 127;
    int b = blockIdx.x >> 7;
    int re_ch = (c < 64) ? c : (64 + c);
    float* pre = buT + (size_t)re_ch * BSr + b * Ss;
    float* pim = pre + (size_t)64 * BSr;
    float2 a = d_abar[c];
    bool rev = (c >= 64);
    int t = threadIdx.x, lane = t & 31, wid = t >> 5;
    int base = t * 32;

    float lre[32], lim[32];
    float xr = 0.0f, xi = 0.0f;
    #pragma unroll
    for (int j = 0; j < 32; j++) {
        int p = base + j;
        int s = rev ? (Ss - 1 - p) : p;
        float br = pre[s], bi = pim[s];
        float nr = fmaf(a.x, xr, fmaf(-a.y, xi, br));
        float ni = fmaf(a.x, xi, fmaf( a.y, xr, bi));
        xr = nr; xi = ni;
        lre[j] = xr; lim[j] = xi;
    }
    // a^32
    float2 a32 = a;
    #pragma unroll
    for (int i = 0; i < 5; i++) {
        float tr = a32.x*a32.x - a32.y*a32.y;
        a32.y = 2.0f*a32.x*a32.y; a32.x = tr;
    }
    // warp pair-scan: (A,E) with op (a1,b1)∘(a2,b2) = (a1a2, a2 b1 + b2)
    float2 pA = a32, pE = make_float2(xr, xi);
    const unsigned full = 0xffffffffu;
    #pragma unroll
    for (int d = 1; d < 32; d <<= 1) {
        float uAx = __shfl_up_sync(full, pA.x, d);
        float uAy = __shfl_up_sync(full, pA.y, d);
        float uEx = __shfl_up_sync(full, pE.x, d);
        float uEy = __shfl_up_sync(full, pE.y, d);
        if (lane >= d) {
            float ex = pA.x*uEx - pA.y*uEy + pE.x;
            float ey = pA.x*uEy + pA.y*uEx + pE.y;
            float ax = pA.x*uAx - pA.y*uAy;
            float ay = pA.x*uAy + pA.y*uAx;
            pE = make_float2(ex, ey); pA = make_float2(ax, ay);
        }
    }
    __shared__ float2 sE[8], sA[8], wpre[8];
    if (lane == 31) { sE[wid] = pE; sA[wid] = pA; }
    // exclusive within warp
    float2 exA, exE;
    exA.x = __shfl_up_sync(full, pA.x, 1);
    exA.y = __shfl_up_sync(full, pA.y, 1);
    exE.x = __shfl_up_sync(full, pE.x, 1);
    exE.y = __shfl_up_sync(full, pE.y, 1);
    if (lane == 0) { exA = make_float2(1.0f, 0.0f); exE = make_float2(0.0f, 0.0f); }
    __syncthreads();
    if (t == 0) {
        float2 P = make_float2(0.0f, 0.0f);
        #pragma unroll
        for (int w = 0; w < 8; w++) {
            wpre[w] = P;
            float px = sA[w].x*P.x - sA[w].y*P.y + sE[w].x;
            float py = sA[w].x*P.y + sA[w].y*P.x + sE[w].y;
            P = make_float2(px, py);
        }
    }
    __syncthreads();
    float2 P = wpre[wid];
    float cx = exA.x*P.x - exA.y*P.y + exE.x;
    float cy = exA.x*P.y + exA.y*P.x + exE.y;
    // apply: x_j = a^{j+1}*carry + local_j
    float2 p = a;
    #pragma unroll
    for (int j = 0; j < 32; j++) {
        float outr = p.x*cx - p.y*cy + lre[j];
        float outi = p.x*cy + p.y*cx + lim[j];
        int pp = base + j;
        int s = rev ? (Ss - 1 - pp) : pp;
        pre[s] = outr; pim[s] = outi;
        float tr = p.x*a.x - p.y*a.y;
        p.y = p.x*a.y + p.y*a.x; p.x = tr;
    }
}

// ---------------- launcher ---------------------------------------------------
extern "C" void kernel_launch(void* const* d_in, const int* in_sizes, int n_in,
                              void* d_out, int out_size) {
    const float* x       = (const float*)d_in[0];
    const float* cond    = (const float*)d_in[1];
    const float* f_la    = (const float*)d_in[2];
    const float* f_ai    = (const float*)d_in[3];
    const float* f_br    = (const float*)d_in[4];
    const float* f_bi    = (const float*)d_in[5];
    const float* f_cr    = (const float*)d_in[6];
    const float* f_ci    = (const float*)d_in[7];
    const float* f_d     = (const float*)d_in[8];
    const float* f_ld    = (const float*)d_in[9];
    const float* b_la    = (const float*)d_in[10];
    const float* b_ai    = (const float*)d_in[11];
    const float* b_br    = (const float*)d_in[12];
    const float* b_bi    = (const float*)d_in[13];
    const float* b_cr    = (const float*)d_in[14];
    const float* b_ci    = (const float*)d_in[15];
    const float* b_d     = (const float*)d_in[16];
    const float* b_ld    = (const float*)d_in[17];
    const float* proj_w  = (const float*)d_in[18];
    const float* proj_b  = (const float*)d_in[19];
    const float* ada_w   = (const float*)d_in[20];
    const float* ada_b   = (const float*)d_in[21];
    const float* mlp_w1  = (const float*)d_in[22];
    const float* mlp_b1  = (const float*)d_in[23];
    const float* mlp_w2  = (const float*)d_in[24];
    const float* mlp_b2  = (const float*)d_in[25];
    float* out = (float*)d_out;

    float *h, *x1, *g, *buT;
    cudaGetSymbolAddress((void**)&h,   d_h);
    cudaGetSymbolAddress((void**)&x1,  d_x1);
    cudaGetSymbolAddress((void**)&g,   d_g);
    cudaGetSymbolAddress((void**)&buT, d_buT);
    float* yscratch = g;   // first 64MB of d_g reused before MLP1

    // prep
    prep_mods_k<<<dim3(12, 4), 256>>>(cond, ada_w, ada_b);
    prep_ssm_k<<<128, 512>>>(f_la, f_ai, f_br, f_bi, f_ld,
                             b_la, b_ai, b_br, b_bi, b_ld);
    prep_wout_k<<<256, 512>>>(f_cr, f_ci, b_cr, b_ci, proj_w);
    prep_wd_k<<<1024, 256>>>(f_d, b_d, proj_w);

    float *wbu, *wout, *wd;
    cudaGetSymbolAddress((void**)&wbu,  d_wbu);
    cudaGetSymbolAddress((void**)&wout, d_wout);
    cudaGetSymbolAddress((void**)&wd,   d_wd);

    // h = LN(x)*(1+sc1)+sh1
    ln_mod_k<<<BSr, 128>>>(x, h, 0);

    // BuT[256][32768] = Wbu @ h^T
    gemm_k<0, 1, 0><<<dim3(BSr/BN, 256/BM), 256>>>(
        wbu, h, buT, 256, BSr, Ff, Ff, Ff, BSr, nullptr, nullptr, nullptr);

    // scan in place
    scan_k<<<512, 256>>>(buT);

    // y-part1 = xs @ Wout  (A = buT transposed)
    gemm_k<1, 0, 0><<<dim3(Ff/BN, BSr/BM), 256>>>(
        buT, wout, yscratch, BSr, Ff, 256, BSr, Ff, Ff, nullptr, nullptr, nullptr);

    // x1 = x + g1*(h @ Wd + y-part1 + proj_b)
    gemm_k<0, 0, 1><<<dim3(Ff/BN, BSr/BM), 256>>>(
        h, wd, x1, BSr, Ff, Ff, Ff, Ff, Ff, yscratch, proj_b, x);

    // h2 = LN(x1)*(1+sc2)+sh2   (reuse d_h)
    ln_mod_k<<<BSr, 128>>>(x1, h, 3*Ff);

    // g = gelu(h2 @ mlp_w1 + b1)
    gemm_k<0, 0, 2><<<dim3(Hh/BN, BSr/BM), 256>>>(
        h, mlp_w1, g, BSr, Hh, Ff, Ff, Hh, Hh, mlp_b1, nullptr, nullptr);

    // out = x1 + g2*(g @ mlp_w2 + b2)
    gemm_k<0, 0, 3><<<dim3(Ff/BN, BSr/BM), 256>>>(
        g, mlp_w2, out, BSr, Ff, Hh, Hh, Ff, Ff, x1, mlp_b2, nullptr);
}

// round 3
// speedup vs baseline: 1.0008x; 1.0008x over previous
#include <cuda_runtime.h>
#include <math.h>

// Problem constants
#define Bb 4
#define Ss 8192
#define Ff 512
#define Nn 64
#define Hh 2048
#define BSr (Bb*Ss)            // 32768 rows

// ---------------- scratch (device globals; no allocations allowed) ----------
__device__ float d_h[BSr*Ff];          // 64MB: h (LN1 out), reused as h2
__device__ float d_x1[BSr*Ff];         // 64MB: first residual result
__device__ float d_g[BSr*Hh];          // 256MB: MLP hidden; first 64MB also used as y-scratch
__device__ float d_buT[256*BSr];       // 32MB: Bu (transposed), scanned in place -> xs
__device__ float d_mods[Bb*6*Ff];      // adaLN modulation
__device__ float d_wbu[256*Ff];        // B_bar combined weight  [ch][f]
__device__ float d_wout[256*Ff];       // C^T @ proj_w combined  [ch][f']
__device__ float d_wd[Ff*Ff];          // diag(D) @ proj_w combined
__device__ float2 d_abar[128];         // per complex channel (0..63 fwd, 64..127 bwd)

// ---------------- prep kernels ----------------------------------------------

// mods = silu(cond) @ ada_w + ada_b     grid(12,4) x 256
__global__ void prep_mods_k(const float* __restrict__ cond,
                            const float* __restrict__ ada_w,
                            const float* __restrict__ ada_b) {
    __shared__ float sc[Ff];
    int b = blockIdx.y;
    for (int i = threadIdx.x; i < Ff; i += 256) {
        float v = cond[b*Ff + i];
        sc[i] = v / (1.0f + expf(-v));
    }
    __syncthreads();
    int j = blockIdx.x * 256 + threadIdx.x;     // 0..3071
    float acc = ada_b[j];
    #pragma unroll 8
    for (int f = 0; f < Ff; f++) acc += sc[f] * ada_w[f*(6*Ff) + j];
    d_mods[b*(6*Ff) + j] = acc;
}

// per-direction SSM discretization -> a_bar, B_bar weight.  grid(128) x 512
__global__ void prep_ssm_k(const float* __restrict__ fla, const float* __restrict__ fai,
                           const float* __restrict__ fbr, const float* __restrict__ fbi,
                           const float* __restrict__ fld,
                           const float* __restrict__ bla, const float* __restrict__ bai,
                           const float* __restrict__ bbr, const float* __restrict__ bbi,
                           const float* __restrict__ bld) {
    int n   = blockIdx.x & 63;
    int dir = blockIdx.x >> 6;
    const float* logAre = dir ? bla : fla;
    const float* Aim    = dir ? bai : fai;
    const float* Bre    = dir ? bbr : fbr;
    const float* Bim    = dir ? bbi : fbi;
    const float* logdt  = dir ? bld : fld;

    float dt   = expf(logdt[n]);
    float Are  = -expf(logAre[n]);
    float Aimv = Aim[n];
    float er   = expf(Are * dt);
    float abr  = er * cosf(Aimv * dt);
    float abi  = er * sinf(Aimv * dt);
    // coef = (a_bar - 1) / (A + 1e-8)
    float dre = Are + 1e-8f, dim = Aimv;
    float den = dre*dre + dim*dim;
    float nre = abr - 1.0f, nim = abi;
    float cre = (nre*dre + nim*dim) / den;
    float cim = (nim*dre - nre*dim) / den;

    if (threadIdx.x == 0) d_abar[dir*64 + n] = make_float2(abr, abi);

    int f = threadIdx.x;                               // 512 threads
    float br = Bre[n*Ff + f], bi = Bim[n*Ff + f];
    d_wbu[(dir*128 + n     )*Ff + f] = cre*br - cim*bi;   // Re(B_bar)
    d_wbu[(dir*128 + 64 + n)*Ff + f] = cre*bi + cim*br;   // Im(B_bar)
}

// W_out[ch][f'] = (+/-) sum_f C[f][n] * proj_w[poff+f][f']   grid(256) x 512
__global__ void prep_wout_k(const float* __restrict__ fcr, const float* __restrict__ fci,
                            const float* __restrict__ bcr, const float* __restrict__ bci,
                            const float* __restrict__ proj_w) {
    int ch  = blockIdx.x;
    int blk = ch >> 6, n = ch & 63;
    const float* C = (blk == 0) ? fcr : (blk == 1) ? fci : (blk == 2) ? bcr : bci;
    float sign = (blk == 1 || blk == 3) ? -1.0f : 1.0f;
    int poff = (blk >= 2) ? Ff : 0;

    __shared__ float sC[Ff];
    for (int i = threadIdx.x; i < Ff; i += 512) sC[i] = C[i*Nn + n];
    __syncthreads();
    int fp = threadIdx.x;
    float acc = 0.0f;
    #pragma unroll 8
    for (int f = 0; f < Ff; f++) acc += sC[f] * proj_w[(poff + f)*Ff + fp];
    d_wout[ch*Ff + fp] = sign * acc;
}

// W_D = diag(D_fwd)@P[0:F] + diag(D_bwd)@P[F:2F]   grid(1024) x 256
__global__ void prep_wd_k(const float* __restrict__ Df, const float* __restrict__ Db,
                          const float* __restrict__ proj_w) {
    int idx = blockIdx.x * 256 + threadIdx.x;   // 0..262143
    int f = idx >> 9;
    d_wd[idx] = Df[f]*proj_w[idx] + Db[f]*proj_w[idx + Ff*Ff];
}

// ---------------- LN + adaLN modulation -------------------------------------
// out = LN(in)*(1+sc)+sh ; moff selects {sh1,sc1} or {sh2,sc2}. grid(32768) x 128
__global__ void ln_mod_k(const float* __restrict__ in, float* __restrict__ out, int moff) {
    int row = blockIdx.x;
    int bb  = row >> 13;
    int tid = threadIdx.x;
    float4 v = ((const float4*)(in + (size_t)row*Ff))[tid];
    float s  = v.x+v.y+v.z+v.w;
    float sq = v.x*v.x + v.y*v.y + v.z*v.z + v.w*v.w;
    #pragma unroll
    for (int o = 16; o > 0; o >>= 1) {
        s  += __shfl_down_sync(0xffffffffu, s,  o);
        sq += __shfl_down_sync(0xffffffffu, sq, o);
    }
    __shared__ float ss[4], ssq[4];
    int w = tid >> 5, l = tid & 31;
    if (l == 0) { ss[w] = s; ssq[w] = sq; }
    __syncthreads();
    if (tid == 0) { ss[0]  = ss[0]+ss[1]+ss[2]+ss[3];
                    ssq[0] = ssq[0]+ssq[1]+ssq[2]+ssq[3]; }
    __syncthreads();
    float mu  = ss[0]  * (1.0f/512.0f);
    float var = ssq[0] * (1.0f/512.0f) - mu*mu;
    float rstd = rsqrtf(var + 1e-5f);
    const float* md = d_mods + bb*(6*Ff) + moff;
    int f = tid*4;
    float4 o4;
    o4.x = (v.x-mu)*rstd*(1.0f+md[Ff+f+0]) + md[f+0];
    o4.y = (v.y-mu)*rstd*(1.0f+md[Ff+f+1]) + md[f+1];
    o4.z = (v.z-mu)*rstd*(1.0f+md[Ff+f+2]) + md[f+2];
    o4.w = (v.w-mu)*rstd*(1.0f+md[Ff+f+3]) + md[f+3];
    ((float4*)(out + (size_t)row*Ff))[tid] = o4;
}

// ---------------- generic tiled fp32 GEMM ------------------------------------
// C[M,N] = A @ B   (TA: 0 = A[m][k] lda=K ; 1 = A stored as AT[k][m], lda = m-stride)
//                  (TB: 0 = B[k][n] ldb=N ; 1 = B stored as BT[n][k], ldb = k-count)
#define BM 128
#define BN 128
#define BK 16

template<int TA, int TB, int EPI>
__global__ __launch_bounds__(256, 2) void gemm_k(
    const float* __restrict__ A, const float* __restrict__ Bm, float* __restrict__ C,
    int M, int N, int K, int lda, int ldb, int ldc,
    const float* __restrict__ aux1, const float* __restrict__ aux2,
    const float* __restrict__ aux3) {
    __shared__ float As[BK][BM + 4];
    __shared__ float Bs[BK][BN + 4];
    int tid = threadIdx.x;
    int tx = tid & 15, ty = tid >> 4;
    int m0 = blockIdx.y * BM, n0 = blockIdx.x * BN;
    float acc[8][8] = {};

    for (int k0 = 0; k0 < K; k0 += BK) {
        // --- load A tile ---
        if (TA == 0) {
            #pragma unroll
            for (int i = 0; i < 2; i++) {
                int idx4 = tid*2 + i;
                int m = idx4 >> 2, kq = idx4 & 3;
                float4 v = *(const float4*)(A + (size_t)(m0+m)*lda + k0 + kq*4);
                As[kq*4+0][m] = v.x; As[kq*4+1][m] = v.y;
                As[kq*4+2][m] = v.z; As[kq*4+3][m] = v.w;
            }
        } else {
            #pragma unroll
            for (int i = 0; i < 2; i++) {
                int idx4 = tid*2 + i;
                int k = idx4 >> 5, mq = idx4 & 31;
                float4 v = *(const float4*)(A + (size_t)(k0+k)*lda + m0 + mq*4);
                *(float4*)&As[k][mq*4] = v;
            }
        }
        // --- load B tile ---
        if (TB == 0) {
            #pragma unroll
            for (int i = 0; i < 2; i++) {
                int idx4 = tid*2 + i;
                int k = idx4 >> 5, nq = idx4 & 31;
                float4 v = *(const float4*)(Bm + (size_t)(k0+k)*ldb + n0 + nq*4);
                *(float4*)&Bs[k][nq*4] = v;
            }
        } else {
            #pragma unroll
            for (int i = 0; i < 2; i++) {
                int idx4 = tid*2 + i;
                int n = idx4 >> 2, kq = idx4 & 3;
                float4 v = *(const float4*)(Bm + (size_t)(n0+n)*ldb + k0 + kq*4);
                Bs[kq*4+0][n] = v.x; Bs[kq*4+1][n] = v.y;
                Bs[kq*4+2][n] = v.z; Bs[kq*4+3][n] = v.w;
            }
        }
        __syncthreads();
        #pragma unroll
        for (int k = 0; k < BK; k++) {
            float a[8], b[8];
            #pragma unroll
            for (int i = 0; i < 8; i++) a[i] = As[k][ty*8 + i];
            #pragma unroll
            for (int j = 0; j < 8; j++) b[j] = Bs[k][tx*8 + j];
            #pragma unroll
            for (int i = 0; i < 8; i++)
                #pragma unroll
                for (int j = 0; j < 8; j++)
                    acc[i][j] = fmaf(a[i], b[j], acc[i][j]);
        }
        __syncthreads();
    }

    // --- epilogue ---
    #pragma unroll
    for (int i = 0; i < 8; i++) {
        int m = m0 + ty*8 + i;
        #pragma unroll
        for (int j = 0; j < 8; j++) {
            int n = n0 + tx*8 + j;
            float v = acc[i][j];
            size_t off = (size_t)m * ldc + n;
            if (EPI == 0) {
                C[off] = v;
            } else if (EPI == 1) {        // x1 = x + g1*(xs_part + h_part + proj_b)
                int bb = m >> 13;
                float y = v + aux1[(size_t)m*Ff + n] + aux2[n];
                float g1 = d_mods[bb*(6*Ff) + 2*Ff + n];
                C[off] = aux3[(size_t)m*Ff + n] + g1 * y;
            } else if (EPI == 2) {        // gelu(tanh approx)(v + b1)
                float x = v + aux1[n];
                float t = tanhf(0.7978845608028654f * (x + 0.044715f * x*x*x));
                C[off] = 0.5f * x * (1.0f + t);
            } else {                      // out = x1 + g2*(v + b2)
                int bb = m >> 13;
                float g2 = d_mods[bb*(6*Ff) + 5*Ff + n];
                C[off] = aux1[off] + g2 * (v + aux2[n]);
            }
        }
    }
}

// ---------------- chunked complex scan (constant multiplier) -----------------
// grid(512) = b*128 + c ; 256 threads, 32 elems/thread, in place on d_buT.
__global__ __launch_bounds__(256) void scan_k(float* __restrict__ buT) {
    int c = blockIdx.x & 127;
    int b = blockIdx.x >> 7;
    int re_ch = (c < 64) ? c : (64 + c);
    float* pre = buT + (size_t)re_ch * BSr + b * Ss;
    float* pim = pre + (size_t)64 * BSr;
    float2 a = d_abar[c];
    bool rev = (c >= 64);
    int t = threadIdx.x, lane = t & 31, wid = t >> 5;
    int base = t * 32;

    float lre[32], lim[32];
    float xr = 0.0f, xi = 0.0f;
    #pragma unroll
    for (int j = 0; j < 32; j++) {
        int p = base + j;
        int s = rev ? (Ss - 1 - p) : p;
        float br = pre[s], bi = pim[s];
        float nr = fmaf(a.x, xr, fmaf(-a.y, xi, br));
        float ni = fmaf(a.x, xi, fmaf( a.y, xr, bi));
        xr = nr; xi = ni;
        lre[j] = xr; lim[j] = xi;
    }
    // a^32
    float2 a32 = a;
    #pragma unroll
    for (int i = 0; i < 5; i++) {
        float tr = a32.x*a32.x - a32.y*a32.y;
        a32.y = 2.0f*a32.x*a32.y; a32.x = tr;
    }
    // warp pair-scan: (A,E) with op (a1,b1)∘(a2,b2) = (a1a2, a2 b1 + b2)
    float2 pA = a32, pE = make_float2(xr, xi);
    const unsigned full = 0xffffffffu;
    #pragma unroll
    for (int d = 1; d < 32; d <<= 1) {
        float uAx = __shfl_up_sync(full, pA.x, d);
        float uAy = __shfl_up_sync(full, pA.y, d);
        float uEx = __shfl_up_sync(full, pE.x, d);
        float uEy = __shfl_up_sync(full, pE.y, d);
        if (lane >= d) {
            float ex = pA.x*uEx - pA.y*uEy + pE.x;
            float ey = pA.x*uEy + pA.y*uEx + pE.y;
            float ax = pA.x*uAx - pA.y*uAy;
            float ay = pA.x*uAy + pA.y*uAx;
            pE = make_float2(ex, ey); pA = make_float2(ax, ay);
        }
    }
    __shared__ float2 sE[8], sA[8], wpre[8];
    if (lane == 31) { sE[wid] = pE; sA[wid] = pA; }
    // exclusive within warp
    float2 exA, exE;
    exA.x = __shfl_up_sync(full, pA.x, 1);
    exA.y = __shfl_up_sync(full, pA.y, 1);
    exE.x = __shfl_up_sync(full, pE.x, 1);
    exE.y = __shfl_up_sync(full, pE.y, 1);
    if (lane == 0) { exA = make_float2(1.0f, 0.0f); exE = make_float2(0.0f, 0.0f); }
    __syncthreads();
    if (t == 0) {
        float2 P = make_float2(0.0f, 0.0f);
        #pragma unroll
        for (int w = 0; w < 8; w++) {
            wpre[w] = P;
            float px = sA[w].x*P.x - sA[w].y*P.y + sE[w].x;
            float py = sA[w].x*P.y + sA[w].y*P.x + sE[w].y;
            P = make_float2(px, py);
        }
    }
    __syncthreads();
    float2 P = wpre[wid];
    float cx = exA.x*P.x - exA.y*P.y + exE.x;
    float cy = exA.x*P.y + exA.y*P.x + exE.y;
    // apply: x_j = a^{j+1}*carry + local_j
    float2 p = a;
    #pragma unroll
    for (int j = 0; j < 32; j++) {
        float outr = p.x*cx - p.y*cy + lre[j];
        float outi = p.x*cy + p.y*cx + lim[j];
        int pp = base + j;
        int s = rev ? (Ss - 1 - pp) : pp;
        pre[s] = outr; pim[s] = outi;
        float tr = p.x*a.x - p.y*a.y;
        p.y = p.x*a.y + p.y*a.x; p.x = tr;
    }
}

// ---------------- launcher ---------------------------------------------------
extern "C" void kernel_launch(void* const* d_in, const int* in_sizes, int n_in,
                              void* d_out, int out_size) {
    const float* x       = (const float*)d_in[0];
    const float* cond    = (const float*)d_in[1];
    const float* f_la    = (const float*)d_in[2];
    const float* f_ai    = (const float*)d_in[3];
    const float* f_br    = (const float*)d_in[4];
    const float* f_bi    = (const float*)d_in[5];
    const float* f_cr    = (const float*)d_in[6];
    const float* f_ci    = (const float*)d_in[7];
    const float* f_d     = (const float*)d_in[8];
    const float* f_ld    = (const float*)d_in[9];
    const float* b_la    = (const float*)d_in[10];
    const float* b_ai    = (const float*)d_in[11];
    const float* b_br    = (const float*)d_in[12];
    const float* b_bi    = (const float*)d_in[13];
    const float* b_cr    = (const float*)d_in[14];
    const float* b_ci    = (const float*)d_in[15];
    const float* b_d     = (const float*)d_in[16];
    const float* b_ld    = (const float*)d_in[17];
    const float* proj_w  = (const float*)d_in[18];
    const float* proj_b  = (const float*)d_in[19];
    const float* ada_w   = (const float*)d_in[20];
    const float* ada_b   = (const float*)d_in[21];
    const float* mlp_w1  = (const float*)d_in[22];
    const float* mlp_b1  = (const float*)d_in[23];
    const float* mlp_w2  = (const float*)d_in[24];
    const float* mlp_b2  = (const float*)d_in[25];
    float* out = (float*)d_out;

    float *h, *x1, *g, *buT;
    cudaGetSymbolAddress((void**)&h,   d_h);
    cudaGetSymbolAddress((void**)&x1,  d_x1);
    cudaGetSymbolAddress((void**)&g,   d_g);
    cudaGetSymbolAddress((void**)&buT, d_buT);
    float* yscratch = g;   // first 64MB of d_g reused before MLP1

    // prep
    prep_mods_k<<<dim3(12, 4), 256>>>(cond, ada_w, ada_b);
    prep_ssm_k<<<128, 512>>>(f_la, f_ai, f_br, f_bi, f_ld,
                             b_la, b_ai, b_br, b_bi, b_ld);
    prep_wout_k<<<256, 512>>>(f_cr, f_ci, b_cr, b_ci, proj_w);
    prep_wd_k<<<1024, 256>>>(f_d, b_d, proj_w);

    float *wbu, *wout, *wd;
    cudaGetSymbolAddress((void**)&wbu,  d_wbu);
    cudaGetSymbolAddress((void**)&wout, d_wout);
    cudaGetSymbolAddress((void**)&wd,   d_wd);

    // h = LN(x)*(1+sc1)+sh1
    ln_mod_k<<<BSr, 128>>>(x, h, 0);

    // BuT[256][32768] = Wbu @ h^T
    gemm_k<0, 1, 0><<<dim3(BSr/BN, 256/BM), 256>>>(
        wbu, h, buT, 256, BSr, Ff, Ff, Ff, BSr, nullptr, nullptr, nullptr);

    // scan in place
    scan_k<<<512, 256>>>(buT);

    // y-part1 = xs @ Wout  (A = buT transposed)
    gemm_k<1, 0, 0><<<dim3(Ff/BN, BSr/BM), 256>>>(
        buT, wout, yscratch, BSr, Ff, 256, BSr, Ff, Ff, nullptr, nullptr, nullptr);

    // x1 = x + g1*(h @ Wd + y-part1 + proj_b)
    gemm_k<0, 0, 1><<<dim3(Ff/BN, BSr/BM), 256>>>(
        h, wd, x1, BSr, Ff, Ff, Ff, Ff, Ff, yscratch, proj_b, x);

    // h2 = LN(x1)*(1+sc2)+sh2   (reuse d_h)
    ln_mod_k<<<BSr, 128>>>(x1, h, 3*Ff);

    // g = gelu(h2 @ mlp_w1 + b1)
    gemm_k<0, 0, 2><<<dim3(Hh/BN, BSr/BM), 256>>>(
        h, mlp_w1, g, BSr, Hh, Ff, Ff, Hh, Hh, mlp_b1, nullptr, nullptr);

    // out = x1 + g2*(g @ mlp_w2 + b2)
    gemm_k<0, 0, 3><<<dim3(Ff/BN, BSr/BM), 256>>>(
        g, mlp_w2, out, BSr, Ff, Hh, Hh, Ff, Ff, x1, mlp_b2, nullptr);
}

// round 5
// speedup vs baseline: 2.4217x; 2.4199x over previous
#include <cuda_runtime.h>
#include <cuda_bf16.h>
#include <math.h>
#include <stdint.h>

#define Bb 4
#define Ss 8192
#define Ff 512
#define Hh 2048
#define BSr 32768
#define KCB 768
typedef __nv_bfloat16 bf16;

__device__ __align__(256) float  d_bu[(size_t)BSr*256];
__device__ __align__(256) bf16   d_comb_hi[(size_t)BSr*KCB];
__device__ __align__(256) bf16   d_comb_lo[(size_t)BSr*KCB];
__device__ __align__(256) bf16   d_h2_hi[(size_t)BSr*Ff];
__device__ __align__(256) bf16   d_h2_lo[(size_t)BSr*Ff];
__device__ __align__(256) bf16   d_g_hi[(size_t)BSr*Hh];
__device__ __align__(256) bf16   d_g_lo[(size_t)BSr*Hh];
__device__ __align__(256) float  d_x1[(size_t)BSr*Ff];
__device__ float  d_mods[Bb*6*Ff];
__device__ float2 d_abar[128];
__device__ float2 d_car[Bb*2*128*64];
__device__ float2 d_off[Bb*2*128*64];
__device__ __align__(256) bf16   d_wbu_hi[256*Ff],  d_wbu_lo[256*Ff];
__device__ __align__(256) bf16   d_wc_hi[Ff*KCB],   d_wc_lo[Ff*KCB];
__device__ __align__(256) bf16   d_w1_hi[(size_t)Hh*Ff], d_w1_lo[(size_t)Hh*Ff];
__device__ __align__(256) bf16   d_w2_hi[(size_t)Ff*Hh], d_w2_lo[(size_t)Ff*Hh];

__device__ __forceinline__ uint32_t s2u(const void* p){
    uint32_t a;
    asm("{ .reg .u64 t; cvta.to.shared.u64 t, %1; cvt.u32.u64 %0, t; }":"=r"(a):"l"(p));
    return a;
}
// swizzle for 64-byte-row tiles: XOR bits[4:6) with bits[7:9)
__device__ __forceinline__ uint32_t sw64(uint32_t o){ return o ^ ((o >> 3) & 0x30u); }
__device__ __forceinline__ void cpa16(uint32_t d, const void* s){
    asm volatile("cp.async.cg.shared.global [%0], [%1], 16;"::"r"(d),"l"(s));
}
#define CPC() asm volatile("cp.async.commit_group;")
#define CPW(n) asm volatile("cp.async.wait_group %0;"::"n"(n))

__device__ __forceinline__ void ldmx4(uint32_t* r, uint32_t a){
    asm volatile("ldmatrix.sync.aligned.m8n8.x4.shared.b16 {%0,%1,%2,%3}, [%4];"
        :"=r"(r[0]),"=r"(r[1]),"=r"(r[2]),"=r"(r[3]):"r"(a));
}
__device__ __forceinline__ void hmma(float* d, const uint32_t* a, const uint32_t* b){
    asm volatile("mma.sync.aligned.m16n8k16.row.col.f32.bf16.bf16.f32 "
        "{%0,%1,%2,%3}, {%4,%5,%6,%7}, {%8,%9}, {%0,%1,%2,%3};"
        : "+f"(d[0]),"+f"(d[1]),"+f"(d[2]),"+f"(d[3])
        : "r"(a[0]),"r"(a[1]),"r"(a[2]),"r"(a[3]),"r"(b[0]),"r"(b[1]));
}
__device__ __forceinline__ void bsplit(float v, bf16& h, bf16& l){
    h = __float2bfloat16(v);
    l = __float2bfloat16(v - __bfloat162float(h));
}

// ---------------- prep ----------------
__global__ void prep_mods_k(const float* __restrict__ cond, const float* __restrict__ aw,
                            const float* __restrict__ ab) {
    __shared__ float sc[Ff];
    int b = blockIdx.y;
    for (int i = threadIdx.x; i < Ff; i += 256) {
        float v = cond[b*Ff + i];
        sc[i] = v / (1.0f + expf(-v));
    }
    __syncthreads();
    int j = blockIdx.x*256 + threadIdx.x;
    float acc = ab[j];
    #pragma unroll 8
    for (int f = 0; f < Ff; f++) acc += sc[f]*aw[f*(6*Ff)+j];
    d_mods[b*(6*Ff)+j] = acc;
}

__global__ void prep_ssm_k(const float* fla, const float* fai, const float* fbr,
                           const float* fbi, const float* fld,
                           const float* bla, const float* bai, const float* bbr,
                           const float* bbi, const float* bld) {
    int n = blockIdx.x & 63, dir = blockIdx.x >> 6;
    const float* la = dir?bla:fla; const float* ai = dir?bai:fai;
    const float* br = dir?bbr:fbr; const float* bi = dir?bbi:fbi;
    const float* ld = dir?bld:fld;
    float dt = expf(ld[n]), Are = -expf(la[n]), Aim = ai[n];
    float er = expf(Are*dt);
    float abr = er*cosf(Aim*dt), abi = er*sinf(Aim*dt);
    float dre = Are + 1e-8f, dim = Aim;
    float den = dre*dre + dim*dim;
    float nre = abr - 1.0f, nim = abi;
    float cre = (nre*dre + nim*dim)/den, cim = (nim*dre - nre*dim)/den;
    if (threadIdx.x == 0) d_abar[dir*64+n] = make_float2(abr, abi);
    int f = threadIdx.x;
    float bre = br[n*Ff+f], bim = bi[n*Ff+f];
    float wr = cre*bre - cim*bim, wi = cre*bim + cim*bre;
    bf16 h, l;
    int rr = (dir*128+n)*Ff+f, ri = (dir*128+64+n)*Ff+f;
    bsplit(wr,h,l); d_wbu_hi[rr]=h; d_wbu_lo[rr]=l;
    bsplit(wi,h,l); d_wbu_hi[ri]=h; d_wbu_lo[ri]=l;
}

__global__ void prep_wout_k(const float* fcr, const float* fci, const float* bcr,
                            const float* bci, const float* pw) {
    int ch = blockIdx.x, blk = ch>>6, n = ch&63;
    const float* C = (blk==0)?fcr:(blk==1)?fci:(blk==2)?bcr:bci;
    float sign = (blk==1||blk==3)?-1.0f:1.0f;
    int poff = (blk>=2)?Ff:0;
    __shared__ float sC[Ff];
    for (int i = threadIdx.x; i < Ff; i += 512) sC[i] = C[i*64+n];
    __syncthreads();
    int fp = threadIdx.x;
    float acc = 0.0f;
    #pragma unroll 8
    for (int f = 0; f < Ff; f++) acc += sC[f]*pw[(poff+f)*Ff+fp];
    bf16 h, l; bsplit(sign*acc, h, l);
    d_wc_hi[(size_t)fp*KCB+ch] = h; d_wc_lo[(size_t)fp*KCB+ch] = l;
}

__global__ void prep_wd_k(const float* Df, const float* Db, const float* pw) {
    int idx = blockIdx.x*256 + threadIdx.x;
    int f = idx>>9, fp = idx&511;
    float v = Df[f]*pw[idx] + Db[f]*pw[idx+Ff*Ff];
    bf16 h, l; bsplit(v, h, l);
    d_wc_hi[(size_t)fp*KCB+256+f] = h; d_wc_lo[(size_t)fp*KCB+256+f] = l;
}

__global__ void transpose_k(const float* __restrict__ s, bf16* dh, bf16* dl, int R, int C) {
    __shared__ float t[32][33];
    int bx = blockIdx.x*32, by = blockIdx.y*32;
    int tx = threadIdx.x & 31, ty = threadIdx.x >> 5;
    #pragma unroll
    for (int i = 0; i < 32; i += 8) t[ty+i][tx] = s[(size_t)(by+ty+i)*C + bx+tx];
    __syncthreads();
    #pragma unroll
    for (int i = 0; i < 32; i += 8) {
        bf16 h, l; bsplit(t[tx][ty+i], h, l);
        size_t o = (size_t)(bx+ty+i)*R + by+tx;
        dh[o] = h; dl[o] = l;
    }
}

__global__ void ln_mod_k(const float* __restrict__ in, bf16* __restrict__ oh,
                         bf16* __restrict__ ol, int ld, int moff) {
    int row = blockIdx.x, bb = row>>13, tid = threadIdx.x;
    float4 v = ((const float4*)(in + (size_t)row*Ff))[tid];
    float s = v.x+v.y+v.z+v.w, sq = v.x*v.x+v.y*v.y+v.z*v.z+v.w*v.w;
    #pragma unroll
    for (int o = 16; o > 0; o >>= 1) {
        s += __shfl_down_sync(~0u, s, o); sq += __shfl_down_sync(~0u, sq, o);
    }
    __shared__ float ss[4], sv[4];
    int w = tid>>5, l = tid&31;
    if (l==0){ ss[w]=s; sv[w]=sq; }
    __syncthreads();
    if (tid==0){ ss[0]+=ss[1]+ss[2]+ss[3]; sv[0]+=sv[1]+sv[2]+sv[3]; }
    __syncthreads();
    float mu = ss[0]*(1.0f/512.0f), var = sv[0]*(1.0f/512.0f) - mu*mu;
    float rs = rsqrtf(var + 1e-5f);
    const float* md = d_mods + bb*(6*Ff) + moff;
    int f = tid*4;
    float o0 = (v.x-mu)*rs*(1.0f+md[Ff+f+0]) + md[f+0];
    float o1 = (v.y-mu)*rs*(1.0f+md[Ff+f+1]) + md[f+1];
    float o2 = (v.z-mu)*rs*(1.0f+md[Ff+f+2]) + md[f+2];
    float o3 = (v.w-mu)*rs*(1.0f+md[Ff+f+3]) + md[f+3];
    size_t base = (size_t)row*ld + f;
    bf16 h, lo;
    bsplit(o0,h,lo); oh[base+0]=h; ol[base+0]=lo;
    bsplit(o1,h,lo); oh[base+1]=h; ol[base+1]=lo;
    bsplit(o2,h,lo); oh[base+2]=h; ol[base+2]=lo;
    bsplit(o3,h,lo); oh[base+3]=h; ol[base+3]=lo;
}

// ---------------- HMMA GEMM: C[M,N] = (Ahi+Alo) @ (Bhi+Blo)^T -----------------
// 128x128 CTA tile, 8 warps of 64x32, K-chunk 32, double-buffered cp.async.
// SMEM per stage: Ah(8K) Al(8K) Bh(8K) Bl(8K) = 32KB. Stage stride 32768.
__device__ __forceinline__ void load_stage(uint32_t b,
    const bf16* __restrict__ Ah, const bf16* __restrict__ Al, int lda,
    const bf16* __restrict__ Bh, const bf16* __restrict__ Bl, int ldb,
    int m0, int n0, int kc, int tid) {
    #pragma unroll
    for (int i = 0; i < 2; i++) {
        int idx = tid + i*256;            // 0..511
        int row = idx >> 2, c16 = idx & 3;
        uint32_t o = sw64((uint32_t)(row*64 + c16*16));
        size_t ga = (size_t)(m0+row)*lda + kc + c16*8;
        size_t gb = (size_t)(n0+row)*ldb + kc + c16*8;
        cpa16(b + o,         Ah + ga);
        cpa16(b + 8192 + o,  Al + ga);
        cpa16(b + 16384 + o, Bh + gb);
        cpa16(b + 24576 + o, Bl + gb);
    }
}

// EPI: 0 fp32 C  1 x1=aux1+g1*(v+aux2)  2 gelu(v+aux2)->bf16 hi/lo  3 aux1+g2*(v+aux2)
template<int EPI>
__global__ __launch_bounds__(256) void gemm_tc(
    const bf16* __restrict__ Ah, const bf16* __restrict__ Al, int lda,
    const bf16* __restrict__ Bh, const bf16* __restrict__ Bl, int ldb, int K,
    float* __restrict__ C, int ldc, const float* __restrict__ aux1,
    const float* __restrict__ aux2, bf16* __restrict__ obh, bf16* __restrict__ obl)
{
    extern __shared__ char dsm[];
    uint32_t sb = (s2u(dsm) + 1023u) & ~1023u;
    int tid = threadIdx.x;
    int n0 = blockIdx.x*128, m0 = blockIdx.y*128;
    int wid = tid>>5, lane = tid&31;
    int wm = wid>>2, wn = wid&3;          // warp tile: rows wm*64, cols wn*32

    float acc[4][4][4];
    #pragma unroll
    for (int a = 0; a < 4; a++)
        #pragma unroll
        for (int bq = 0; bq < 4; bq++)
            #pragma unroll
            for (int r = 0; r < 4; r++) acc[a][bq][r] = 0.0f;

    const int NC = K >> 5;
    load_stage(sb, Ah, Al, lda, Bh, Bl, ldb, m0, n0, 0, tid);
    CPC();
    for (int c = 0; c < NC; c++) {
        uint32_t cur = sb + (uint32_t)(c & 1)*32768u;
        if (c + 1 < NC) {
            load_stage(sb + (uint32_t)((c+1)&1)*32768u, Ah, Al, lda, Bh, Bl, ldb,
                       m0, n0, (c+1)<<5, tid);
            CPC();
            CPW(1);
        } else {
            CPW(0);
        }
        __syncthreads();
        #pragma unroll
        for (int ks = 0; ks < 2; ks++) {
            uint32_t afh[4][4], afl[4][4], bfh[4][2], bfl[4][2];
            #pragma unroll
            for (int mt = 0; mt < 4; mt++) {
                int row = wm*64 + mt*16 + (lane & 15);
                int ch  = ks*2 + (lane >> 4);
                uint32_t o = sw64((uint32_t)(row*64 + ch*16));
                ldmx4(afh[mt], cur + o);
                ldmx4(afl[mt], cur + 8192 + o);
            }
            #pragma unroll
            for (int bp = 0; bp < 2; bp++) {
                int mi = lane >> 3;
                int row = wn*32 + bp*16 + (mi >> 1)*8 + (lane & 7);
                int ch  = ks*2 + (mi & 1);
                uint32_t o = sw64((uint32_t)(row*64 + ch*16));
                uint32_t r[4];
                ldmx4(r, cur + 16384 + o);
                bfh[bp*2][0]=r[0]; bfh[bp*2][1]=r[1]; bfh[bp*2+1][0]=r[2]; bfh[bp*2+1][1]=r[3];
                ldmx4(r, cur + 24576 + o);
                bfl[bp*2][0]=r[0]; bfl[bp*2][1]=r[1]; bfl[bp*2+1][0]=r[2]; bfl[bp*2+1][1]=r[3];
            }
            #pragma unroll
            for (int mt = 0; mt < 4; mt++)
                #pragma unroll
                for (int nt = 0; nt < 4; nt++) {
                    hmma(acc[mt][nt], afh[mt], bfh[nt]);
                    hmma(acc[mt][nt], afh[mt], bfl[nt]);
                    hmma(acc[mt][nt], afl[mt], bfh[nt]);
                }
        }
        __syncthreads();
    }

    // epilogue: direct register -> global
    int g = lane >> 2, tig = lane & 3;
    #pragma unroll
    for (int mt = 0; mt < 4; mt++) {
        #pragma unroll
        for (int nt = 0; nt < 4; nt++) {
            int n = n0 + wn*32 + nt*8 + tig*2;
            #pragma unroll
            for (int half = 0; half < 2; half++) {
                int m = m0 + wm*64 + mt*16 + g + half*8;
                float v0 = acc[mt][nt][half*2+0], v1 = acc[mt][nt][half*2+1];
                if (EPI == 0) {
                    float2 o = {v0, v1};
                    *(float2*)&C[(size_t)m*ldc + n] = o;
                } else if (EPI == 1 || EPI == 3) {
                    int bb = m >> 13;
                    const float* md = d_mods + bb*(6*Ff) + (EPI==1 ? 2*Ff : 5*Ff);
                    float2 o;
                    o.x = aux1[(size_t)m*Ff + n+0] + md[n+0]*(v0 + aux2[n+0]);
                    o.y = aux1[(size_t)m*Ff + n+1] + md[n+1]*(v1 + aux2[n+1]);
                    *(float2*)&C[(size_t)m*ldc + n] = o;
                } else {
                    bf16 hp[2], lp[2];
                    #pragma unroll
                    for (int i = 0; i < 2; i++) {
                        float xg = (i ? v1 : v0) + aux2[n+i];
                        float t = tanhf(0.7978845608028654f*(xg + 0.044715f*xg*xg*xg));
                        float gv = 0.5f*xg*(1.0f + t);
                        bsplit(gv, hp[i], lp[i]);
                    }
                    *(uint32_t*)&obh[(size_t)m*ldc + n] = *(uint32_t*)hp;
                    *(uint32_t*)&obl[(size_t)m*ldc + n] = *(uint32_t*)lp;
                }
            }
        }
    }
}

// ---------------- 3-phase scan over row-major Bu[32768][256] -----------------
__global__ __launch_bounds__(64) void scan_local_k() {
    int c = threadIdx.x, chunk = blockIdx.x, b = blockIdx.y, dir = blockIdx.z;
    int rc = dir ? 128+c : c, ic = rc+64;
    float2 a = d_abar[dir*64+c];
    float* p = d_bu + (size_t)(b*Ss + chunk*64)*256;
    float re[64], im[64];
    #pragma unroll
    for (int j = 0; j < 64; j++) {
        int s = dir ? 63-j : j;
        re[j] = p[s*256+rc]; im[j] = p[s*256+ic];
    }
    float xr = 0.0f, xi = 0.0f;
    #pragma unroll
    for (int j = 0; j < 64; j++) {
        float nr = a.x*xr - a.y*xi + re[j];
        float ni = a.x*xi + a.y*xr + im[j];
        xr = nr; xi = ni; re[j] = xr; im[j] = xi;
    }
    #pragma unroll
    for (int j = 0; j < 64; j++) {
        int s = dir ? 63-j : j;
        p[s*256+rc] = re[j]; p[s*256+ic] = im[j];
    }
    d_car[(((size_t)(b*2+dir))*128 + chunk)*64 + c] = make_float2(xr, xi);
}

__global__ void scan_combine_k() {
    int tid = threadIdx.x;
    int b = tid>>7, dir = (tid>>6)&1, c = tid&63;
    float2 a = d_abar[dir*64+c], a64 = a;
    #pragma unroll
    for (int i = 0; i < 6; i++) {
        float t = a64.x*a64.x - a64.y*a64.y;
        a64.y = 2.0f*a64.x*a64.y; a64.x = t;
    }
    size_t base = ((size_t)(b*2+dir))*128*64 + c;
    float ox = 0.0f, oy = 0.0f;
    for (int k = 0; k < 128; k++) {
        int ch = dir ? 127-k : k;
        float2 cr = d_car[base + (size_t)ch*64];
        d_off[base + (size_t)ch*64] = make_float2(ox, oy);
        float nx = a64.x*ox - a64.y*oy + cr.x;
        float ny = a64.x*oy + a64.y*ox + cr.y;
        ox = nx; oy = ny;
    }
}

__global__ __launch_bounds__(64) void scan_apply_k() {
    int c = threadIdx.x, chunk = blockIdx.x, b = blockIdx.y, dir = blockIdx.z;
    int rc = dir ? 128+c : c, ic = rc+64;
    float2 a = d_abar[dir*64+c];
    float2 O = d_off[(((size_t)(b*2+dir))*128 + chunk)*64 + c];
    const float* p = d_bu + (size_t)(b*Ss + chunk*64)*256;
    size_t rb = (size_t)(b*Ss + chunk*64);
    float px = a.x, py = a.y;
    #pragma unroll
    for (int j = 0; j < 64; j++) {
        int s = dir ? 63-j : j;
        float vr = p[s*256+rc] + (px*O.x - py*O.y);
        float vi = p[s*256+ic] + (px*O.y + py*O.x);
        float np = px*a.x - py*a.y;
        py = px*a.y + py*a.x; px = np;
        size_t ro = (rb + s)*KCB;
        bf16 h, l;
        bsplit(vr,h,l); d_comb_hi[ro+rc]=h; d_comb_lo[ro+rc]=l;
        bsplit(vi,h,l); d_comb_hi[ro+ic]=h; d_comb_lo[ro+ic]=l;
    }
}

// ---------------- launcher ----------------------------------------------------
extern "C" void kernel_launch(void* const* d_in, const int* in_sizes, int n_in,
                              void* d_out, int out_size) {
    const float* x      = (const float*)d_in[0];
    const float* cond   = (const float*)d_in[1];
    const float* f_la   = (const float*)d_in[2];
    const float* f_ai   = (const float*)d_in[3];
    const float* f_br   = (const float*)d_in[4];
    const float* f_bi   = (const float*)d_in[5];
    const float* f_cr   = (const float*)d_in[6];
    const float* f_ci   = (const float*)d_in[7];
    const float* f_d    = (const float*)d_in[8];
    const float* f_ld   = (const float*)d_in[9];
    const float* b_la   = (const float*)d_in[10];
    const float* b_ai   = (const float*)d_in[11];
    const float* b_br   = (const float*)d_in[12];
    const float* b_bi   = (const float*)d_in[13];
    const float* b_cr   = (const float*)d_in[14];
    const float* b_ci   = (const float*)d_in[15];
    const float* b_d    = (const float*)d_in[16];
    const float* b_ld   = (const float*)d_in[17];
    const float* proj_w = (const float*)d_in[18];
    const float* proj_b = (const float*)d_in[19];
    const float* ada_w  = (const float*)d_in[20];
    const float* ada_b  = (const float*)d_in[21];
    const float* mlp_w1 = (const float*)d_in[22];
    const float* mlp_b1 = (const float*)d_in[23];
    const float* mlp_w2 = (const float*)d_in[24];
    const float* mlp_b2 = (const float*)d_in[25];
    float* out = (float*)d_out;

    const int DSM = 2*32768 + 1024;
    cudaFuncSetAttribute(gemm_tc<0>, cudaFuncAttributeMaxDynamicSharedMemorySize, DSM);
    cudaFuncSetAttribute(gemm_tc<1>, cudaFuncAttributeMaxDynamicSharedMemorySize, DSM);
    cudaFuncSetAttribute(gemm_tc<2>, cudaFuncAttributeMaxDynamicSharedMemorySize, DSM);
    cudaFuncSetAttribute(gemm_tc<3>, cudaFuncAttributeMaxDynamicSharedMemorySize, DSM);

    float *bu, *x1; bf16 *chh, *chl, *h2h, *h2l, *gh, *gl;
    bf16 *wbh, *wbl, *wch, *wcl, *w1h, *w1l, *w2h, *w2l;
    cudaGetSymbolAddress((void**)&bu, d_bu);
    cudaGetSymbolAddress((void**)&x1, d_x1);
    cudaGetSymbolAddress((void**)&chh, d_comb_hi);
    cudaGetSymbolAddress((void**)&chl, d_comb_lo);
    cudaGetSymbolAddress((void**)&h2h, d_h2_hi);
    cudaGetSymbolAddress((void**)&h2l, d_h2_lo);
    cudaGetSymbolAddress((void**)&gh, d_g_hi);
    cudaGetSymbolAddress((void**)&gl, d_g_lo);
    cudaGetSymbolAddress((void**)&wbh, d_wbu_hi);
    cudaGetSymbolAddress((void**)&wbl, d_wbu_lo);
    cudaGetSymbolAddress((void**)&wch, d_wc_hi);
    cudaGetSymbolAddress((void**)&wcl, d_wc_lo);
    cudaGetSymbolAddress((void**)&w1h, d_w1_hi);
    cudaGetSymbolAddress((void**)&w1l, d_w1_lo);
    cudaGetSymbolAddress((void**)&w2h, d_w2_hi);
    cudaGetSymbolAddress((void**)&w2l, d_w2_lo);

    prep_mods_k<<<dim3(12,4), 256>>>(cond, ada_w, ada_b);
    prep_ssm_k<<<128, 512>>>(f_la,f_ai,f_br,f_bi,f_ld, b_la,b_ai,b_br,b_bi,b_ld);
    prep_wout_k<<<256, 512>>>(f_cr, f_ci, b_cr, b_ci, proj_w);
    prep_wd_k<<<1024, 256>>>(f_d, b_d, proj_w);
    transpose_k<<<dim3(Hh/32, Ff/32), 256>>>(mlp_w1, w1h, w1l, Ff, Hh);
    transpose_k<<<dim3(Ff/32, Hh/32), 256>>>(mlp_w2, w2h, w2l, Hh, Ff);

    // h = modulated LN(x)  -> comb cols 256..767 (bf16 hi/lo)
    ln_mod_k<<<BSr, 128>>>(x, chh+256, chl+256, KCB, 0);

    // Bu[32768,256] = h @ Wbu^T
    gemm_tc<0><<<dim3(2,256), 256, DSM>>>(chh+256, chl+256, KCB, wbh, wbl, Ff, Ff,
                                          bu, 256, nullptr, nullptr, nullptr, nullptr);
    scan_local_k<<<dim3(128,4,2), 64>>>();
    scan_combine_k<<<1, 512>>>();
    scan_apply_k<<<dim3(128,4,2), 64>>>();

    // x1 = x + g1*(comb @ Wc^T + proj_b)
    gemm_tc<1><<<dim3(4,256), 256, DSM>>>(chh, chl, KCB, wch, wcl, KCB, KCB,
                                          x1, Ff, x, proj_b, nullptr, nullptr);

    // h2 = modulated LN(x1)
    ln_mod_k<<<BSr, 128>>>(x1, h2h, h2l, Ff, 3*Ff);

    // g = gelu(h2 @ W1^T + b1) -> bf16 hi/lo
    gemm_tc<2><<<dim3(16,256), 256, DSM>>>(h2h, h2l, Ff, w1h, w1l, Ff, Ff,
                                           nullptr, Hh, nullptr, mlp_b1, gh, gl);

    // out = x1 + g2*(g @ W2^T + b2)
    gemm_tc<3><<<dim3(4,256), 256, DSM>>>(gh, gl, Hh, w2h, w2l, Hh, Hh,
                                          out, Ff, x1, mlp_b2, nullptr, nullptr);
}

// round 6
// speedup vs baseline: 5.7595x; 2.3783x over previous
#include <cuda_runtime.h>
#include <cuda_fp16.h>
#include <math.h>
#include <stdint.h>

#define Bb 4
#define Ss 8192
#define Ff 512
#define Hh 2048
#define BSr 32768
#define KCB 768
typedef __half fp16;

__device__ __align__(256) float  d_bu[(size_t)BSr*256];
__device__ __align__(256) fp16   d_comb[(size_t)BSr*KCB];   // cols 0..255 xs, 256..767 h
__device__ __align__(256) fp16   d_h2[(size_t)BSr*Ff];
__device__ __align__(256) fp16   d_g[(size_t)BSr*Hh];
__device__ __align__(256) float  d_x1[(size_t)BSr*Ff];
__device__ float  d_mods[Bb*6*Ff];
__device__ float2 d_abar[128];
__device__ float2 d_car[Bb*2*128*64];
__device__ float2 d_off[Bb*2*128*64];
__device__ __align__(256) fp16   d_wbu[256*Ff];
__device__ __align__(256) fp16   d_wc[Ff*KCB];
__device__ __align__(256) fp16   d_w1[(size_t)Hh*Ff];
__device__ __align__(256) fp16   d_w2[(size_t)Ff*Hh];

__device__ __forceinline__ uint32_t s2u(const void* p){
    uint32_t a;
    asm("{ .reg .u64 t; cvta.to.shared.u64 t, %1; cvt.u32.u64 %0, t; }":"=r"(a):"l"(p));
    return a;
}
__device__ __forceinline__ uint32_t sw64(uint32_t o){ return o ^ ((o >> 3) & 0x30u); }
__device__ __forceinline__ void cpa16(uint32_t d, const void* s){
    asm volatile("cp.async.cg.shared.global [%0], [%1], 16;"::"r"(d),"l"(s));
}
#define CPC() asm volatile("cp.async.commit_group;")
#define CPW(n) asm volatile("cp.async.wait_group %0;"::"n"(n))

__device__ __forceinline__ void ldmx4(uint32_t* r, uint32_t a){
    asm volatile("ldmatrix.sync.aligned.m8n8.x4.shared.b16 {%0,%1,%2,%3}, [%4];"
        :"=r"(r[0]),"=r"(r[1]),"=r"(r[2]),"=r"(r[3]):"r"(a));
}
__device__ __forceinline__ void hmma(float* d, const uint32_t* a, const uint32_t* b){
    asm volatile("mma.sync.aligned.m16n8k16.row.col.f32.f16.f16.f32 "
        "{%0,%1,%2,%3}, {%4,%5,%6,%7}, {%8,%9}, {%0,%1,%2,%3};"
        : "+f"(d[0]),"+f"(d[1]),"+f"(d[2]),"+f"(d[3])
        : "r"(a[0]),"r"(a[1]),"r"(a[2]),"r"(a[3]),"r"(b[0]),"r"(b[1]));
}

// ---------------- prep ----------------
__global__ void prep_mods_k(const float* __restrict__ cond, const float* __restrict__ aw,
                            const float* __restrict__ ab) {
    __shared__ float sc[Ff];
    int b = blockIdx.y;
    for (int i = threadIdx.x; i < Ff; i += 256) {
        float v = cond[b*Ff + i];
        sc[i] = v / (1.0f + expf(-v));
    }
    __syncthreads();
    int j = blockIdx.x*256 + threadIdx.x;
    float acc = ab[j];
    #pragma unroll 8
    for (int f = 0; f < Ff; f++) acc += sc[f]*aw[f*(6*Ff)+j];
    d_mods[b*(6*Ff)+j] = acc;
}

__global__ void prep_ssm_k(const float* fla, const float* fai, const float* fbr,
                           const float* fbi, const float* fld,
                           const float* bla, const float* bai, const float* bbr,
                           const float* bbi, const float* bld) {
    int n = blockIdx.x & 63, dir = blockIdx.x >> 6;
    const float* la = dir?bla:fla; const float* ai = dir?bai:fai;
    const float* br = dir?bbr:fbr; const float* bi = dir?bbi:fbi;
    const float* ld = dir?bld:fld;
    float dt = expf(ld[n]), Are = -expf(la[n]), Aim = ai[n];
    float er = expf(Are*dt);
    float abr = er*cosf(Aim*dt), abi = er*sinf(Aim*dt);
    float dre = Are + 1e-8f, dim = Aim;
    float den = dre*dre + dim*dim;
    float nre = abr - 1.0f, nim = abi;
    float cre = (nre*dre + nim*dim)/den, cim = (nim*dre - nre*dim)/den;
    if (threadIdx.x == 0) d_abar[dir*64+n] = make_float2(abr, abi);
    int f = threadIdx.x;
    float bre = br[n*Ff+f], bim = bi[n*Ff+f];
    d_wbu[(dir*128+n)*Ff+f]    = __float2half_rn(cre*bre - cim*bim);
    d_wbu[(dir*128+64+n)*Ff+f] = __float2half_rn(cre*bim + cim*bre);
}

__global__ void prep_wout_k(const float* fcr, const float* fci, const float* bcr,
                            const float* bci, const float* pw) {
    int ch = blockIdx.x, blk = ch>>6, n = ch&63;
    const float* C = (blk==0)?fcr:(blk==1)?fci:(blk==2)?bcr:bci;
    float sign = (blk==1||blk==3)?-1.0f:1.0f;
    int poff = (blk>=2)?Ff:0;
    __shared__ float sC[Ff];
    for (int i = threadIdx.x; i < Ff; i += 512) sC[i] = C[i*64+n];
    __syncthreads();
    int fp = threadIdx.x;
    float acc = 0.0f;
    #pragma unroll 8
    for (int f = 0; f < Ff; f++) acc += sC[f]*pw[(poff+f)*Ff+fp];
    d_wc[(size_t)fp*KCB+ch] = __float2half_rn(sign*acc);
}

__global__ void prep_wd_k(const float* Df, const float* Db, const float* pw) {
    int idx = blockIdx.x*256 + threadIdx.x;
    int f = idx>>9, fp = idx&511;
    float v = Df[f]*pw[idx] + Db[f]*pw[idx+Ff*Ff];
    d_wc[(size_t)fp*KCB+256+f] = __float2half_rn(v);
}

__global__ void transpose_k(const float* __restrict__ s, fp16* dh, int R, int C) {
    __shared__ float t[32][33];
    int bx = blockIdx.x*32, by = blockIdx.y*32;
    int tx = threadIdx.x & 31, ty = threadIdx.x >> 5;
    #pragma unroll
    for (int i = 0; i < 32; i += 8) t[ty+i][tx] = s[(size_t)(by+ty+i)*C + bx+tx];
    __syncthreads();
    #pragma unroll
    for (int i = 0; i < 32; i += 8)
        dh[(size_t)(bx+ty+i)*R + by+tx] = __float2half_rn(t[tx][ty+i]);
}

__global__ void ln_mod_k(const float* __restrict__ in, fp16* __restrict__ oh,
                         int ld, int moff) {
    int row = blockIdx.x, bb = row>>13, tid = threadIdx.x;
    float4 v = ((const float4*)(in + (size_t)row*Ff))[tid];
    float s = v.x+v.y+v.z+v.w, sq = v.x*v.x+v.y*v.y+v.z*v.z+v.w*v.w;
    #pragma unroll
    for (int o = 16; o > 0; o >>= 1) {
        s += __shfl_down_sync(~0u, s, o); sq += __shfl_down_sync(~0u, sq, o);
    }
    __shared__ float ss[4], sv[4];
    int w = tid>>5, l = tid&31;
    if (l==0){ ss[w]=s; sv[w]=sq; }
    __syncthreads();
    if (tid==0){ ss[0]+=ss[1]+ss[2]+ss[3]; sv[0]+=sv[1]+sv[2]+sv[3]; }
    __syncthreads();
    float mu = ss[0]*(1.0f/512.0f), var = sv[0]*(1.0f/512.0f) - mu*mu;
    float rs = rsqrtf(var + 1e-5f);
    const float* md = d_mods + bb*(6*Ff) + moff;
    int f = tid*4;
    float o0 = (v.x-mu)*rs*(1.0f+md[Ff+f+0]) + md[f+0];
    float o1 = (v.y-mu)*rs*(1.0f+md[Ff+f+1]) + md[f+1];
    float o2 = (v.z-mu)*rs*(1.0f+md[Ff+f+2]) + md[f+2];
    float o3 = (v.w-mu)*rs*(1.0f+md[Ff+f+3]) + md[f+3];
    fp16 h4[4] = {__float2half_rn(o0), __float2half_rn(o1),
                  __float2half_rn(o2), __float2half_rn(o3)};
    *(uint2*)&oh[(size_t)row*ld + f] = *(uint2*)h4;
}

// ---------------- HMMA GEMM: C[M,N] = A @ B^T  (fp16 in, fp32 accum) ----------
// 128x128 CTA tile, 8 warps of 64x32, K-chunk 32, double-buffered cp.async.
// SMEM per stage: A 8KB + B 8KB = 16KB.
__device__ __forceinline__ void load_stage(uint32_t b,
    const fp16* __restrict__ A, int lda, const fp16* __restrict__ B, int ldb,
    int m0, int n0, int kc, int tid) {
    #pragma unroll
    for (int i = 0; i < 2; i++) {
        int idx = tid + i*256;            // 0..511
        int row = idx >> 2, c16 = idx & 3;
        uint32_t o = sw64((uint32_t)(row*64 + c16*16));
        cpa16(b + o,        A + (size_t)(m0+row)*lda + kc + c16*8);
        cpa16(b + 8192 + o, B + (size_t)(n0+row)*ldb + kc + c16*8);
    }
}

// EPI: 0 fp32 C  1 x1=aux1+g1*(v+aux2)  2 gelu(v+aux2)->fp16  3 aux1+g2*(v+aux2)
template<int EPI>
__global__ __launch_bounds__(256, 2) void gemm_tc(
    const fp16* __restrict__ A, int lda,
    const fp16* __restrict__ B, int ldb, int K,
    float* __restrict__ C, int ldc, const float* __restrict__ aux1,
    const float* __restrict__ aux2, fp16* __restrict__ obh)
{
    extern __shared__ char dsm[];
    uint32_t sb = (s2u(dsm) + 1023u) & ~1023u;
    int tid = threadIdx.x;
    int n0 = blockIdx.x*128, m0 = blockIdx.y*128;
    int wid = tid>>5, lane = tid&31;
    int wm = wid>>2, wn = wid&3;

    float acc[4][4][4];
    #pragma unroll
    for (int a = 0; a < 4; a++)
        #pragma unroll
        for (int bq = 0; bq < 4; bq++)
            #pragma unroll
            for (int r = 0; r < 4; r++) acc[a][bq][r] = 0.0f;

    const int NC = K >> 5;
    load_stage(sb, A, lda, B, ldb, m0, n0, 0, tid);
    CPC();
    for (int c = 0; c < NC; c++) {
        uint32_t cur = sb + (uint32_t)(c & 1)*16384u;
        if (c + 1 < NC) {
            load_stage(sb + (uint32_t)((c+1)&1)*16384u, A, lda, B, ldb,
                       m0, n0, (c+1)<<5, tid);
            CPC();
            CPW(1);
        } else {
            CPW(0);
        }
        __syncthreads();
        #pragma unroll
        for (int ks = 0; ks < 2; ks++) {
            uint32_t af[4][4], bf[4][2];
            #pragma unroll
            for (int mt = 0; mt < 4; mt++) {
                int row = wm*64 + mt*16 + (lane & 15);
                int ch  = ks*2 + (lane >> 4);
                ldmx4(af[mt], cur + sw64((uint32_t)(row*64 + ch*16)));
            }
            #pragma unroll
            for (int bp = 0; bp < 2; bp++) {
                int mi = lane >> 3;
                int row = wn*32 + bp*16 + (mi >> 1)*8 + (lane & 7);
                int ch  = ks*2 + (mi & 1);
                uint32_t r[4];
                ldmx4(r, cur + 8192 + sw64((uint32_t)(row*64 + ch*16)));
                bf[bp*2][0]=r[0]; bf[bp*2][1]=r[1]; bf[bp*2+1][0]=r[2]; bf[bp*2+1][1]=r[3];
            }
            #pragma unroll
            for (int mt = 0; mt < 4; mt++)
                #pragma unroll
                for (int nt = 0; nt < 4; nt++)
                    hmma(acc[mt][nt], af[mt], bf[nt]);
        }
        __syncthreads();
    }

    int g = lane >> 2, tig = lane & 3;
    #pragma unroll
    for (int mt = 0; mt < 4; mt++) {
        #pragma unroll
        for (int nt = 0; nt < 4; nt++) {
            int n = n0 + wn*32 + nt*8 + tig*2;
            #pragma unroll
            for (int half = 0; half < 2; half++) {
                int m = m0 + wm*64 + mt*16 + g + half*8;
                float v0 = acc[mt][nt][half*2+0], v1 = acc[mt][nt][half*2+1];
                if (EPI == 0) {
                    float2 o = {v0, v1};
                    *(float2*)&C[(size_t)m*ldc + n] = o;
                } else if (EPI == 1 || EPI == 3) {
                    int bb = m >> 13;
                    const float* md = d_mods + bb*(6*Ff) + (EPI==1 ? 2*Ff : 5*Ff);
                    float2 o;
                    o.x = aux1[(size_t)m*Ff + n+0] + md[n+0]*(v0 + aux2[n+0]);
                    o.y = aux1[(size_t)m*Ff + n+1] + md[n+1]*(v1 + aux2[n+1]);
                    *(float2*)&C[(size_t)m*ldc + n] = o;
                } else {
                    fp16 hp[2];
                    #pragma unroll
                    for (int i = 0; i < 2; i++) {
                        float xg = (i ? v1 : v0) + aux2[n+i];
                        float t = tanhf(0.7978845608028654f*(xg + 0.044715f*xg*xg*xg));
                        hp[i] = __float2half_rn(0.5f*xg*(1.0f + t));
                    }
                    *(uint32_t*)&obh[(size_t)m*ldc + n] = *(uint32_t*)hp;
                }
            }
        }
    }
}

// ---------------- 3-phase scan over row-major Bu[32768][256] -----------------
__global__ __launch_bounds__(64) void scan_local_k() {
    int c = threadIdx.x, chunk = blockIdx.x, b = blockIdx.y, dir = blockIdx.z;
    int rc = dir ? 128+c : c, ic = rc+64;
    float2 a = d_abar[dir*64+c];
    float* p = d_bu + (size_t)(b*Ss + chunk*64)*256;
    float re[64], im[64];
    #pragma unroll
    for (int j = 0; j < 64; j++) {
        int s = dir ? 63-j : j;
        re[j] = p[s*256+rc]; im[j] = p[s*256+ic];
    }
    float xr = 0.0f, xi = 0.0f;
    #pragma unroll
    for (int j = 0; j < 64; j++) {
        float nr = a.x*xr - a.y*xi + re[j];
        float ni = a.x*xi + a.y*xr + im[j];
        xr = nr; xi = ni; re[j] = xr; im[j] = xi;
    }
    #pragma unroll
    for (int j = 0; j < 64; j++) {
        int s = dir ? 63-j : j;
        p[s*256+rc] = re[j]; p[s*256+ic] = im[j];
    }
    d_car[(((size_t)(b*2+dir))*128 + chunk)*64 + c] = make_float2(xr, xi);
}

__global__ void scan_combine_k() {
    int tid = threadIdx.x;
    int b = tid>>7, dir = (tid>>6)&1, c = tid&63;
    float2 a = d_abar[dir*64+c], a64 = a;
    #pragma unroll
    for (int i = 0; i < 6; i++) {
        float t = a64.x*a64.x - a64.y*a64.y;
        a64.y = 2.0f*a64.x*a64.y; a64.x = t;
    }
    size_t base = ((size_t)(b*2+dir))*128*64 + c;
    float ox = 0.0f, oy = 0.0f;
    for (int k = 0; k < 128; k++) {
        int ch = dir ? 127-k : k;
        float2 cr = d_car[base + (size_t)ch*64];
        d_off[base + (size_t)ch*64] = make_float2(ox, oy);
        float nx = a64.x*ox - a64.y*oy + cr.x;
        float ny = a64.x*oy + a64.y*ox + cr.y;
        ox = nx; oy = ny;
    }
}

__global__ __launch_bounds__(64) void scan_apply_k() {
    int c = threadIdx.x, chunk = blockIdx.x, b = blockIdx.y, dir = blockIdx.z;
    int rc = dir ? 128+c : c, ic = rc+64;
    float2 a = d_abar[dir*64+c];
    float2 O = d_off[(((size_t)(b*2+dir))*128 + chunk)*64 + c];
    const float* p = d_bu + (size_t)(b*Ss + chunk*64)*256;
    size_t rb = (size_t)(b*Ss + chunk*64);
    float px = a.x, py = a.y;
    #pragma unroll
    for (int j = 0; j < 64; j++) {
        int s = dir ? 63-j : j;
        float vr = p[s*256+rc] + (px*O.x - py*O.y);
        float vi = p[s*256+ic] + (px*O.y + py*O.x);
        float np = px*a.x - py*a.y;
        py = px*a.y + py*a.x; px = np;
        size_t ro = (rb + s)*KCB;
        d_comb[ro+rc] = __float2half_rn(vr);
        d_comb[ro+ic] = __float2half_rn(vi);
    }
}

// ---------------- launcher ----------------------------------------------------
extern "C" void kernel_launch(void* const* d_in, const int* in_sizes, int n_in,
                              void* d_out, int out_size) {
    const float* x      = (const float*)d_in[0];
    const float* cond   = (const float*)d_in[1];
    const float* f_la   = (const float*)d_in[2];
    const float* f_ai   = (const float*)d_in[3];
    const float* f_br   = (const float*)d_in[4];
    const float* f_bi   = (const float*)d_in[5];
    const float* f_cr   = (const float*)d_in[6];
    const float* f_ci   = (const float*)d_in[7];
    const float* f_d    = (const float*)d_in[8];
    const float* f_ld   = (const float*)d_in[9];
    const float* b_la   = (const float*)d_in[10];
    const float* b_ai   = (const float*)d_in[11];
    const float* b_br   = (const float*)d_in[12];
    const float* b_bi   = (const float*)d_in[13];
    const float* b_cr   = (const float*)d_in[14];
    const float* b_ci   = (const float*)d_in[15];
    const float* b_d    = (const float*)d_in[16];
    const float* b_ld   = (const float*)d_in[17];
    const float* proj_w = (const float*)d_in[18];
    const float* proj_b = (const float*)d_in[19];
    const float* ada_w  = (const float*)d_in[20];
    const float* ada_b  = (const float*)d_in[21];
    const float* mlp_w1 = (const float*)d_in[22];
    const float* mlp_b1 = (const float*)d_in[23];
    const float* mlp_w2 = (const float*)d_in[24];
    const float* mlp_b2 = (const float*)d_in[25];
    float* out = (float*)d_out;

    const int DSM = 2*16384 + 1024;

    float *bu, *x1; fp16 *comb, *h2, *g, *wbu, *wc, *w1, *w2;
    cudaGetSymbolAddress((void**)&bu, d_bu);
    cudaGetSymbolAddress((void**)&x1, d_x1);
    cudaGetSymbolAddress((void**)&comb, d_comb);
    cudaGetSymbolAddress((void**)&h2, d_h2);
    cudaGetSymbolAddress((void**)&g, d_g);
    cudaGetSymbolAddress((void**)&wbu, d_wbu);
    cudaGetSymbolAddress((void**)&wc, d_wc);
    cudaGetSymbolAddress((void**)&w1, d_w1);
    cudaGetSymbolAddress((void**)&w2, d_w2);

    prep_mods_k<<<dim3(12,4), 256>>>(cond, ada_w, ada_b);
    prep_ssm_k<<<128, 512>>>(f_la,f_ai,f_br,f_bi,f_ld, b_la,b_ai,b_br,b_bi,b_ld);
    prep_wout_k<<<256, 512>>>(f_cr, f_ci, b_cr, b_ci, proj_w);
    prep_wd_k<<<1024, 256>>>(f_d, b_d, proj_w);
    transpose_k<<<dim3(Hh/32, Ff/32), 256>>>(mlp_w1, w1, Ff, Hh);
    transpose_k<<<dim3(Ff/32, Hh/32), 256>>>(mlp_w2, w2, Hh, Ff);

    // h = modulated LN(x)  -> comb cols 256..767
    ln_mod_k<<<BSr, 128>>>(x, comb+256, KCB, 0);

    // Bu[32768,256] = h @ Wbu^T
    gemm_tc<0><<<dim3(2,256), 256, DSM>>>(comb+256, KCB, wbu, Ff, Ff,
                                          bu, 256, nullptr, nullptr, nullptr);
    scan_local_k<<<dim3(128,4,2), 64>>>();
    scan_combine_k<<<1, 512>>>();
    scan_apply_k<<<dim3(128,4,2), 64>>>();

    // x1 = x + g1*(comb @ Wc^T + proj_b)
    gemm_tc<1><<<dim3(4,256), 256, DSM>>>(comb, KCB, wc, KCB, KCB,
                                          x1, Ff, x, proj_b, nullptr);

    // h2 = modulated LN(x1)
    ln_mod_k<<<BSr, 128>>>(x1, h2, Ff, 3*Ff);

    // g = gelu(h2 @ W1^T + b1) -> fp16
    gemm_tc<2><<<dim3(16,256), 256, DSM>>>(h2, Ff, w1, Ff, Ff,
                                           nullptr, Hh, nullptr, mlp_b1, g);

    // out = x1 + g2*(g @ W2^T + b2)
    gemm_tc<3><<<dim3(4,256), 256, DSM>>>(g, Hh, w2, Hh, Hh,
                                          out, Ff, x1, mlp_b2, nullptr);
}

// round 7
// speedup vs baseline: 6.1323x; 1.0647x over previous
#include <cuda_runtime.h>
#include <cuda_fp16.h>
#include <math.h>
#include <stdint.h>

#define Bb 4
#define Ss 8192
#define Ff 512
#define Hh 2048
#define BSr 32768
#define KCB 768
typedef __half fp16;

__device__ __align__(256) float  d_bu[(size_t)BSr*256];
__device__ __align__(256) fp16   d_comb[(size_t)BSr*KCB];   // cols 0..255 xs, 256..767 h
__device__ __align__(256) fp16   d_h2[(size_t)BSr*Ff];
__device__ __align__(256) fp16   d_g[(size_t)BSr*Hh];
__device__ __align__(256) float  d_x1[(size_t)BSr*Ff];
__device__ float  d_mods[Bb*6*Ff];
__device__ float2 d_abar[128];
__device__ float2 d_car[Bb*2*128*64];
__device__ float2 d_off[Bb*2*128*64];
__device__ __align__(256) fp16   d_wbu[256*Ff];
__device__ __align__(256) fp16   d_wc[Ff*KCB];
__device__ __align__(256) fp16   d_w1[(size_t)Hh*Ff];
__device__ __align__(256) fp16   d_w2[(size_t)Ff*Hh];

__device__ __forceinline__ uint32_t s2u(const void* p){
    uint32_t a;
    asm("{ .reg .u64 t; cvta.to.shared.u64 t, %1; cvt.u32.u64 %0, t; }":"=r"(a):"l"(p));
    return a;
}
__device__ __forceinline__ uint32_t sw64(uint32_t o){ return o ^ ((o >> 3) & 0x30u); }
__device__ __forceinline__ void cpa16(uint32_t d, const void* s){
    asm volatile("cp.async.cg.shared.global [%0], [%1], 16;"::"r"(d),"l"(s));
}
#define CPC() asm volatile("cp.async.commit_group;")
#define CPW(n) asm volatile("cp.async.wait_group %0;"::"n"(n))

__device__ __forceinline__ void ldmx4(uint32_t* r, uint32_t a){
    asm volatile("ldmatrix.sync.aligned.m8n8.x4.shared.b16 {%0,%1,%2,%3}, [%4];"
        :"=r"(r[0]),"=r"(r[1]),"=r"(r[2]),"=r"(r[3]):"r"(a));
}
__device__ __forceinline__ void hmma(float* d, const uint32_t* a, const uint32_t* b){
    asm volatile("mma.sync.aligned.m16n8k16.row.col.f32.f16.f16.f32 "
        "{%0,%1,%2,%3}, {%4,%5,%6,%7}, {%8,%9}, {%0,%1,%2,%3};"
        : "+f"(d[0]),"+f"(d[1]),"+f"(d[2]),"+f"(d[3])
        : "r"(a[0]),"r"(a[1]),"r"(a[2]),"r"(a[3]),"r"(b[0]),"r"(b[1]));
}

// ---------------- prep ----------------
__global__ void prep_mods_k(const float* __restrict__ cond, const float* __restrict__ aw,
                            const float* __restrict__ ab) {
    __shared__ float sc[Ff];
    int b = blockIdx.y;
    for (int i = threadIdx.x; i < Ff; i += 256) {
        float v = cond[b*Ff + i];
        sc[i] = v / (1.0f + expf(-v));
    }
    __syncthreads();
    int j = blockIdx.x*256 + threadIdx.x;
    float acc = ab[j];
    #pragma unroll 8
    for (int f = 0; f < Ff; f++) acc += sc[f]*aw[f*(6*Ff)+j];
    d_mods[b*(6*Ff)+j] = acc;
}

__global__ void prep_ssm_k(const float* fla, const float* fai, const float* fbr,
                           const float* fbi, const float* fld,
                           const float* bla, const float* bai, const float* bbr,
                           const float* bbi, const float* bld) {
    int n = blockIdx.x & 63, dir = blockIdx.x >> 6;
    const float* la = dir?bla:fla; const float* ai = dir?bai:fai;
    const float* br = dir?bbr:fbr; const float* bi = dir?bbi:fbi;
    const float* ld = dir?bld:fld;
    float dt = expf(ld[n]), Are = -expf(la[n]), Aim = ai[n];
    float er = expf(Are*dt);
    float abr = er*cosf(Aim*dt), abi = er*sinf(Aim*dt);
    float dre = Are + 1e-8f, dim = Aim;
    float den = dre*dre + dim*dim;
    float nre = abr - 1.0f, nim = abi;
    float cre = (nre*dre + nim*dim)/den, cim = (nim*dre - nre*dim)/den;
    if (threadIdx.x == 0) d_abar[dir*64+n] = make_float2(abr, abi);
    int f = threadIdx.x;
    float bre = br[n*Ff+f], bim = bi[n*Ff+f];
    d_wbu[(dir*128+n)*Ff+f]    = __float2half_rn(cre*bre - cim*bim);
    d_wbu[(dir*128+64+n)*Ff+f] = __float2half_rn(cre*bim + cim*bre);
}

// merged: blocks 0..255 build xs-part of Wc (C^T P), blocks 256..767 build h-part
__global__ void prep_wc_k(const float* fcr, const float* fci, const float* bcr,
                          const float* bci, const float* Df, const float* Db,
                          const float* pw) {
    if (blockIdx.x < 256) {
        int ch = blockIdx.x, blk = ch>>6, n = ch&63;
        const float* C = (blk==0)?fcr:(blk==1)?fci:(blk==2)?bcr:bci;
        float sign = (blk==1||blk==3)?-1.0f:1.0f;
        int poff = (blk>=2)?Ff:0;
        __shared__ float sC[Ff];
        for (int i = threadIdx.x; i < Ff; i += 512) sC[i] = C[i*64+n];
        __syncthreads();
        int fp = threadIdx.x;
        float acc = 0.0f;
        #pragma unroll 8
        for (int f = 0; f < Ff; f++) acc += sC[f]*pw[(poff+f)*Ff+fp];
        d_wc[(size_t)fp*KCB+ch] = __float2half_rn(sign*acc);
    } else {
        int idx = (blockIdx.x - 256)*512 + threadIdx.x;   // 0..262143
        int f = idx>>9, fp = idx&511;
        float v = Df[f]*pw[idx] + Db[f]*pw[idx+Ff*Ff];
        d_wc[(size_t)fp*KCB+256+f] = __float2half_rn(v);
    }
}

// merged transpose for w1 (2048x512 <- 512x2048) and w2 (512x2048 <- 2048x512)
__global__ void transpose_k(const float* __restrict__ s1, fp16* d1,
                            const float* __restrict__ s2, fp16* d2) {
    __shared__ float t[32][33];
    int id = blockIdx.x;
    const float* s; fp16* d; int R, C, bx, by;
    if (id < 1024) { s = s1; d = d1; R = Ff; C = Hh; bx = (id & 63)*32; by = (id >> 6)*32; }
    else { id -= 1024; s = s2; d = d2; R = Hh; C = Ff; bx = (id & 15)*32; by = (id >> 4)*32; }
    int tx = threadIdx.x & 31, ty = threadIdx.x >> 5;
    #pragma unroll
    for (int i = 0; i < 32; i += 8) t[ty+i][tx] = s[(size_t)(by+ty+i)*C + bx+tx];
    __syncthreads();
    #pragma unroll
    for (int i = 0; i < 32; i += 8)
        d[(size_t)(bx+ty+i)*R + by+tx] = __float2half_rn(t[tx][ty+i]);
}

__global__ void ln_mod_k(const float* __restrict__ in, fp16* __restrict__ oh,
                         int ld, int moff) {
    int row = blockIdx.x, bb = row>>13, tid = threadIdx.x;
    float4 v = ((const float4*)(in + (size_t)row*Ff))[tid];
    float s = v.x+v.y+v.z+v.w, sq = v.x*v.x+v.y*v.y+v.z*v.z+v.w*v.w;
    #pragma unroll
    for (int o = 16; o > 0; o >>= 1) {
        s += __shfl_down_sync(~0u, s, o); sq += __shfl_down_sync(~0u, sq, o);
    }
    __shared__ float ss[4], sv[4];
    int w = tid>>5, l = tid&31;
    if (l==0){ ss[w]=s; sv[w]=sq; }
    __syncthreads();
    if (tid==0){ ss[0]+=ss[1]+ss[2]+ss[3]; sv[0]+=sv[1]+sv[2]+sv[3]; }
    __syncthreads();
    float mu = ss[0]*(1.0f/512.0f), var = sv[0]*(1.0f/512.0f) - mu*mu;
    float rs = rsqrtf(var + 1e-5f);
    const float* md = d_mods + bb*(6*Ff) + moff;
    int f = tid*4;
    float o0 = (v.x-mu)*rs*(1.0f+md[Ff+f+0]) + md[f+0];
    float o1 = (v.y-mu)*rs*(1.0f+md[Ff+f+1]) + md[f+1];
    float o2 = (v.z-mu)*rs*(1.0f+md[Ff+f+2]) + md[f+2];
    float o3 = (v.w-mu)*rs*(1.0f+md[Ff+f+3]) + md[f+3];
    fp16 h4[4] = {__float2half_rn(o0), __float2half_rn(o1),
                  __float2half_rn(o2), __float2half_rn(o3)};
    *(uint2*)&oh[(size_t)row*ld + f] = *(uint2*)h4;
}

// ---------------- HMMA GEMM: C[M,N] = A @ B^T  (fp16 in, fp32 accum) ----------
// 128x128 CTA tile, 8 warps of 64x32, K-chunk 64 (two 16KB sub-stages),
// double-buffered cp.async: stage = 32KB (A0 B0 A1 B1 of 8KB each).
__device__ __forceinline__ void load_sub(uint32_t b,
    const fp16* __restrict__ A, int lda, const fp16* __restrict__ B, int ldb,
    int m0, int n0, int kc, int tid) {
    #pragma unroll
    for (int i = 0; i < 2; i++) {
        int idx = tid + i*256;            // 0..511
        int row = idx >> 2, c16 = idx & 3;
        uint32_t o = sw64((uint32_t)(row*64 + c16*16));
        cpa16(b + o,        A + (size_t)(m0+row)*lda + kc + c16*8);
        cpa16(b + 8192 + o, B + (size_t)(n0+row)*ldb + kc + c16*8);
    }
}
__device__ __forceinline__ void load_stage(uint32_t b,
    const fp16* __restrict__ A, int lda, const fp16* __restrict__ B, int ldb,
    int m0, int n0, int kc, int tid) {
    load_sub(b,         A, lda, B, ldb, m0, n0, kc,      tid);
    load_sub(b + 16384, A, lda, B, ldb, m0, n0, kc + 32, tid);
}

// EPI: 0 fp32 C  1 x1=aux1+g1*(v+aux2)  2 gelu(v+aux2)->fp16  3 aux1+g2*(v+aux2)
template<int EPI>
__global__ __launch_bounds__(256, 2) void gemm_tc(
    const fp16* __restrict__ A, int lda,
    const fp16* __restrict__ B, int ldb, int K,
    float* __restrict__ C, int ldc, const float* __restrict__ aux1,
    const float* __restrict__ aux2, fp16* __restrict__ obh)
{
    extern __shared__ char dsm[];
    uint32_t sb = (s2u(dsm) + 1023u) & ~1023u;
    int tid = threadIdx.x;
    int n0 = blockIdx.x*128, m0 = blockIdx.y*128;
    int wid = tid>>5, lane = tid&31;
    int wm = wid>>2, wn = wid&3;

    float acc[4][4][4];
    #pragma unroll
    for (int a = 0; a < 4; a++)
        #pragma unroll
        for (int bq = 0; bq < 4; bq++)
            #pragma unroll
            for (int r = 0; r < 4; r++) acc[a][bq][r] = 0.0f;

    const int NC = K >> 6;
    load_stage(sb, A, lda, B, ldb, m0, n0, 0, tid);
    CPC();
    for (int c = 0; c < NC; c++) {
        uint32_t cur = sb + (uint32_t)(c & 1)*32768u;
        if (c + 1 < NC) {
            load_stage(sb + (uint32_t)((c+1)&1)*32768u, A, lda, B, ldb,
                       m0, n0, (c+1)<<6, tid);
            CPC();
            CPW(1);
        } else {
            CPW(0);
        }
        __syncthreads();
        #pragma unroll
        for (int ks4 = 0; ks4 < 4; ks4++) {
            uint32_t sub = cur + (uint32_t)(ks4 >> 1)*16384u;
            int ks = ks4 & 1;
            uint32_t af[4][4], bf[4][2];
            #pragma unroll
            for (int mt = 0; mt < 4; mt++) {
                int row = wm*64 + mt*16 + (lane & 15);
                int ch  = ks*2 + (lane >> 4);
                ldmx4(af[mt], sub + sw64((uint32_t)(row*64 + ch*16)));
            }
            #pragma unroll
            for (int bp = 0; bp < 2; bp++) {
                int mi = lane >> 3;
                int row = wn*32 + bp*16 + (mi >> 1)*8 + (lane & 7);
                int ch  = ks*2 + (mi & 1);
                uint32_t r[4];
                ldmx4(r, sub + 8192 + sw64((uint32_t)(row*64 + ch*16)));
                bf[bp*2][0]=r[0]; bf[bp*2][1]=r[1]; bf[bp*2+1][0]=r[2]; bf[bp*2+1][1]=r[3];
            }
            #pragma unroll
            for (int mt = 0; mt < 4; mt++)
                #pragma unroll
                for (int nt = 0; nt < 4; nt++)
                    hmma(acc[mt][nt], af[mt], bf[nt]);
        }
        __syncthreads();
    }

    int g = lane >> 2, tig = lane & 3;
    #pragma unroll
    for (int mt = 0; mt < 4; mt++) {
        #pragma unroll
        for (int nt = 0; nt < 4; nt++) {
            int n = n0 + wn*32 + nt*8 + tig*2;
            #pragma unroll
            for (int half = 0; half < 2; half++) {
                int m = m0 + wm*64 + mt*16 + g + half*8;
                float v0 = acc[mt][nt][half*2+0], v1 = acc[mt][nt][half*2+1];
                if (EPI == 0) {
                    float2 o = {v0, v1};
                    *(float2*)&C[(size_t)m*ldc + n] = o;
                } else if (EPI == 1 || EPI == 3) {
                    int bb = m >> 13;
                    const float* md = d_mods + bb*(6*Ff) + (EPI==1 ? 2*Ff : 5*Ff);
                    float2 o;
                    o.x = aux1[(size_t)m*Ff + n+0] + md[n+0]*(v0 + aux2[n+0]);
                    o.y = aux1[(size_t)m*Ff + n+1] + md[n+1]*(v1 + aux2[n+1]);
                    *(float2*)&C[(size_t)m*ldc + n] = o;
                } else {
                    fp16 hp[2];
                    #pragma unroll
                    for (int i = 0; i < 2; i++) {
                        float xg = (i ? v1 : v0) + aux2[n+i];
                        float t = tanhf(0.7978845608028654f*(xg + 0.044715f*xg*xg*xg));
                        hp[i] = __float2half_rn(0.5f*xg*(1.0f + t));
                    }
                    *(uint32_t*)&obh[(size_t)m*ldc + n] = *(uint32_t*)hp;
                }
            }
        }
    }
}

// ---------------- 3-phase scan over row-major Bu[32768][256] -----------------
__global__ __launch_bounds__(64) void scan_local_k() {
    int c = threadIdx.x, chunk = blockIdx.x, b = blockIdx.y, dir = blockIdx.z;
    int rc = dir ? 128+c : c, ic = rc+64;
    float2 a = d_abar[dir*64+c];
    float* p = d_bu + (size_t)(b*Ss + chunk*64)*256;
    float re[64], im[64];
    #pragma unroll
    for (int j = 0; j < 64; j++) {
        int s = dir ? 63-j : j;
        re[j] = p[s*256+rc]; im[j] = p[s*256+ic];
    }
    float xr = 0.0f, xi = 0.0f;
    #pragma unroll
    for (int j = 0; j < 64; j++) {
        float nr = a.x*xr - a.y*xi + re[j];
        float ni = a.x*xi + a.y*xr + im[j];
        xr = nr; xi = ni; re[j] = xr; im[j] = xi;
    }
    #pragma unroll
    for (int j = 0; j < 64; j++) {
        int s = dir ? 63-j : j;
        p[s*256+rc] = re[j]; p[s*256+ic] = im[j];
    }
    d_car[(((size_t)(b*2+dir))*128 + chunk)*64 + c] = make_float2(xr, xi);
}

__global__ void scan_combine_k() {
    int tid = threadIdx.x;
    int b = tid>>7, dir = (tid>>6)&1, c = tid&63;
    float2 a = d_abar[dir*64+c], a64 = a;
    #pragma unroll
    for (int i = 0; i < 6; i++) {
        float t = a64.x*a64.x - a64.y*a64.y;
        a64.y = 2.0f*a64.x*a64.y; a64.x = t;
    }
    size_t base = ((size_t)(b*2+dir))*128*64 + c;
    float ox = 0.0f, oy = 0.0f;
    for (int k = 0; k < 128; k++) {
        int ch = dir ? 127-k : k;
        float2 cr = d_car[base + (size_t)ch*64];
        d_off[base + (size_t)ch*64] = make_float2(ox, oy);
        float nx = a64.x*ox - a64.y*oy + cr.x;
        float ny = a64.x*oy + a64.y*ox + cr.y;
        ox = nx; oy = ny;
    }
}

__global__ __launch_bounds__(64) void scan_apply_k() {
    int c = threadIdx.x, chunk = blockIdx.x, b = blockIdx.y, dir = blockIdx.z;
    int rc = dir ? 128+c : c, ic = rc+64;
    float2 a = d_abar[dir*64+c];
    float2 O = d_off[(((size_t)(b*2+dir))*128 + chunk)*64 + c];
    const float* p = d_bu + (size_t)(b*Ss + chunk*64)*256;
    size_t rb = (size_t)(b*Ss + chunk*64);
    float px = a.x, py = a.y;
    #pragma unroll
    for (int j = 0; j < 64; j++) {
        int s = dir ? 63-j : j;
        float vr = p[s*256+rc] + (px*O.x - py*O.y);
        float vi = p[s*256+ic] + (px*O.y + py*O.x);
        float np = px*a.x - py*a.y;
        py = px*a.y + py*a.x; px = np;
        size_t ro = (rb + s)*KCB;
        d_comb[ro+rc] = __float2half_rn(vr);
        d_comb[ro+ic] = __float2half_rn(vi);
    }
}

// ---------------- launcher ----------------------------------------------------
extern "C" void kernel_launch(void* const* d_in, const int* in_sizes, int n_in,
                              void* d_out, int out_size) {
    const float* x      = (const float*)d_in[0];
    const float* cond   = (const float*)d_in[1];
    const float* f_la   = (const float*)d_in[2];
    const float* f_ai   = (const float*)d_in[3];
    const float* f_br   = (const float*)d_in[4];
    const float* f_bi   = (const float*)d_in[5];
    const float* f_cr   = (const float*)d_in[6];
    const float* f_ci   = (const float*)d_in[7];
    const float* f_d    = (const float*)d_in[8];
    const float* f_ld   = (const float*)d_in[9];
    const float* b_la   = (const float*)d_in[10];
    const float* b_ai   = (const float*)d_in[11];
    const float* b_br   = (const float*)d_in[12];
    const float* b_bi   = (const float*)d_in[13];
    const float* b_cr   = (const float*)d_in[14];
    const float* b_ci   = (const float*)d_in[15];
    const float* b_d    = (const float*)d_in[16];
    const float* b_ld   = (const float*)d_in[17];
    const float* proj_w = (const float*)d_in[18];
    const float* proj_b = (const float*)d_in[19];
    const float* ada_w  = (const float*)d_in[20];
    const float* ada_b  = (const float*)d_in[21];
    const float* mlp_w1 = (const float*)d_in[22];
    const float* mlp_b1 = (const float*)d_in[23];
    const float* mlp_w2 = (const float*)d_in[24];
    const float* mlp_b2 = (const float*)d_in[25];
    float* out = (float*)d_out;

    const int DSM = 2*32768 + 1024;
    cudaFuncSetAttribute(gemm_tc<0>, cudaFuncAttributeMaxDynamicSharedMemorySize, DSM);
    cudaFuncSetAttribute(gemm_tc<1>, cudaFuncAttributeMaxDynamicSharedMemorySize, DSM);
    cudaFuncSetAttribute(gemm_tc<2>, cudaFuncAttributeMaxDynamicSharedMemorySize, DSM);
    cudaFuncSetAttribute(gemm_tc<3>, cudaFuncAttributeMaxDynamicSharedMemorySize, DSM);

    float *bu, *x1; fp16 *comb, *h2, *g, *wbu, *wc, *w1, *w2;
    cudaGetSymbolAddress((void**)&bu, d_bu);
    cudaGetSymbolAddress((void**)&x1, d_x1);
    cudaGetSymbolAddress((void**)&comb, d_comb);
    cudaGetSymbolAddress((void**)&h2, d_h2);
    cudaGetSymbolAddress((void**)&g, d_g);
    cudaGetSymbolAddress((void**)&wbu, d_wbu);
    cudaGetSymbolAddress((void**)&wc, d_wc);
    cudaGetSymbolAddress((void**)&w1, d_w1);
    cudaGetSymbolAddress((void**)&w2, d_w2);

    // 5 launches before the first GEMM so ncu (-s 5 -c 1) captures gemm_tc<0>
    prep_mods_k<<<dim3(12,4), 256>>>(cond, ada_w, ada_b);                       // 1
    prep_ssm_k<<<128, 512>>>(f_la,f_ai,f_br,f_bi,f_ld, b_la,b_ai,b_br,b_bi,b_ld); // 2
    prep_wc_k<<<768, 512>>>(f_cr, f_ci, b_cr, b_ci, f_d, b_d, proj_w);          // 3
    transpose_k<<<2048, 256>>>(mlp_w1, w1, mlp_w2, w2);                         // 4
    ln_mod_k<<<BSr, 128>>>(x, comb+256, KCB, 0);                                // 5

    // Bu[32768,256] = h @ Wbu^T          (6th launch -> ncu capture)
    gemm_tc<0><<<dim3(2,256), 256, DSM>>>(comb+256, KCB, wbu, Ff, Ff,
                                          bu, 256, nullptr, nullptr, nullptr);
    scan_local_k<<<dim3(128,4,2), 64>>>();
    scan_combine_k<<<1, 512>>>();
    scan_apply_k<<<dim3(128,4,2), 64>>>();

    // x1 = x + g1*(comb @ Wc^T + proj_b)
    gemm_tc<1><<<dim3(4,256), 256, DSM>>>(comb, KCB, wc, KCB, KCB,
                                          x1, Ff, x, proj_b, nullptr);

    // h2 = modulated LN(x1)
    ln_mod_k<<<BSr, 128>>>(x1, h2, Ff, 3*Ff);

    // g = gelu(h2 @ W1^T + b1) -> fp16
    gemm_tc<2><<<dim3(16,256), 256, DSM>>>(h2, Ff, w1, Ff, Ff,
                                           nullptr, Hh, nullptr, mlp_b1, g);

    // out = x1 + g2*(g @ W2^T + b2)
    gemm_tc<3><<<dim3(4,256), 256, DSM>>>(g, Hh, w2, Hh, Hh,
                                          out, Ff, x1, mlp_b2, nullptr);
}